// round 8
// baseline (speedup 1.0000x reference)
#include <cuda_runtime.h>
#include <cuda_bf16.h>
#include <math.h>
#include <stdint.h>

#define Bb 4
#define SQ 1024
#define SKV 2048
#define DM 1024
#define NH 16
#define DH 64

// ---------------------------------------------------------------------------
// Scratch (device globals; no runtime allocation). Total = 112.5 MiB,
// identical to the R2 build that passed with delta=0. Never passed as
// kernel arguments from host — always referenced inside device code.
// ---------------------------------------------------------------------------
__device__ __align__(16) float g_Q[Bb*NH*SQ*DH];     // [B,H,Sq,Dh] (rope'd, scaled)
__device__ __align__(16) float g_K[Bb*NH*SKV*DH];    // [B,H,Skv,Dh] (rope'd)
__device__ __align__(16) float g_V[Bb*NH*SKV*DH];    // [B,H,Skv,Dh]
__device__ __align__(16) float g_ctx[Bb*SQ*DM];      // [B,Sq,H*Dh]
__device__ __align__(16) float g_proj[Bb*SQ*DM];     // [B,Sq,DM]
__device__ __align__(16) float g_rc[SKV*32];         // rope cos [s][pair]
__device__ __align__(16) float g_rs[SKV*32];         // rope sin [s][pair]

// ---------------------------------------------------------------------------
// mma.sync bf16 (sm_80+ path; compiles under compute_100)
// D(16x8) += A(16x16,row) * B(16x8,col), fp32 accum
// ---------------------------------------------------------------------------
#define MMA_BF16(d, a, b) \
    asm volatile("mma.sync.aligned.m16n8k16.row.col.f32.bf16.bf16.f32 " \
        "{%0,%1,%2,%3}, {%4,%5,%6,%7}, {%8,%9}, {%0,%1,%2,%3};" \
        : "+f"((d)[0]), "+f"((d)[1]), "+f"((d)[2]), "+f"((d)[3]) \
        : "r"((a)[0]), "r"((a)[1]), "r"((a)[2]), "r"((a)[3]), \
          "r"((b)[0]), "r"((b)[1]))

// ---------------------------------------------------------------------------
// RoPE table (double precision; immune to --use_fast_math)
// ---------------------------------------------------------------------------
__global__ void rope_table_k() {
    int idx = blockIdx.x * blockDim.x + threadIdx.x;
    if (idx >= SKV * 32) return;
    int s = idx >> 5, p = idx & 31;
    double inv = pow(10000.0, -(double)(2 * p) / 64.0);
    double ang = (double)s * inv;
    g_rc[idx] = (float)cos(ang);
    g_rs[idx] = (float)sin(ang);
}

// ---------------------------------------------------------------------------
// split helper: 2 floats -> bf16x2 (hi) + bf16x2 (residual)
// ---------------------------------------------------------------------------
__device__ __forceinline__ void split2(float a, float b, uint32_t& hp, uint32_t& lp) {
    __nv_bfloat16 ha = __float2bfloat16(a), hb = __float2bfloat16(b);
    float la = a - __bfloat162float(ha);
    float lb = b - __bfloat162float(hb);
    __nv_bfloat16 hla = __float2bfloat16(la), hlb = __float2bfloat16(lb);
    hp = (uint32_t)__bfloat16_as_ushort(ha) | ((uint32_t)__bfloat16_as_ushort(hb) << 16);
    lp = (uint32_t)__bfloat16_as_ushort(hla) | ((uint32_t)__bfloat16_as_ushort(hlb) << 16);
}

// ---------------------------------------------------------------------------
// mma.sync GEMM: C[M,1024] = A[M,1024] @ W[1024,1024], fp32 in/out.
// A and W read as fp32 and split to bf16 hi/lo DURING smem staging
// (W transposed during staging: sB[n][k] = W[k][n]).
// 3-term split: Ah*Wh + Ah*Wl + Al*Wh -> ~2^-16 relative accuracy.
// Block tile 64x64, K-chunk 32, 8 warps (2x4), warp tile 32x16.
// MODE 0: V   MODE 1: Q (rope + 0.125)   MODE 2: K (rope)   MODE 3: proj
// ---------------------------------------------------------------------------
#define KC   32
#define TSTR 40   // 80B rows: conflict-free fragment loads

template<int MODE>
__global__ __launch_bounds__(256)
void mgemm_k(const float* __restrict__ A, const float* __restrict__ W, int S) {
    __shared__ __align__(16) __nv_bfloat16 sAh[64][TSTR], sAl[64][TSTR];
    __shared__ __align__(16) __nv_bfloat16 sBh[64][TSTR], sBl[64][TSTR];

    const float* Ain = (MODE == 3) ? g_ctx : A;   // internal symbol only in device code

    int tid = threadIdx.x, wid = tid >> 5, lane = tid & 31;
    int wr = wid >> 2, wc = wid & 3;          // 2 x 4 warp grid
    int qr = lane >> 2, qc = lane & 3;        // quad row/col
    const int arow0 = blockIdx.y * 64, bcol0 = blockIdx.x * 64;

    float acc[2][2][4];
    #pragma unroll
    for (int mi = 0; mi < 2; mi++)
        #pragma unroll
        for (int ni = 0; ni < 2; ni++)
            #pragma unroll
            for (int e = 0; e < 4; e++) acc[mi][ni][e] = 0.f;

    for (int kt = 0; kt < DM; kt += KC) {
        // --- stage A chunk [64][32]: split fp32 -> bf16 h/l, packed stores
        {
            int r = tid >> 2, c = (tid & 3) * 8;
            const float* src = Ain + (size_t)(arow0 + r) * DM + kt + c;
            float v[8];
            *(float4*)(v)     = *(const float4*)(src);
            *(float4*)(v + 4) = *(const float4*)(src + 4);
            uint32_t hp[4], lp[4];
            #pragma unroll
            for (int i = 0; i < 4; i++) split2(v[2*i], v[2*i+1], hp[i], lp[i]);
            *(uint4*)&sAh[r][c] = *(uint4*)hp;
            *(uint4*)&sAl[r][c] = *(uint4*)lp;
        }
        // --- stage W chunk transposed: sB[n][k] = W[kt+k][bcol0+n]
        {
            int k = tid >> 3, n0 = (tid & 7) * 8;
            const float* src = W + (size_t)(kt + k) * DM + bcol0 + n0;
            float v[8];
            *(float4*)(v)     = *(const float4*)(src);
            *(float4*)(v + 4) = *(const float4*)(src + 4);
            #pragma unroll
            for (int j = 0; j < 8; j++) {
                __nv_bfloat16 h = __float2bfloat16(v[j]);
                sBh[n0 + j][k] = h;
                sBl[n0 + j][k] = __float2bfloat16(v[j] - __bfloat162float(h));
            }
        }
        __syncthreads();

        #pragma unroll
        for (int k16 = 0; k16 < KC; k16 += 16) {
            int c0 = k16 + qc * 2;
            uint32_t af[2][4], bf[2][2];

            // pass 1: Ah * Wh
            #pragma unroll
            for (int mi = 0; mi < 2; mi++) {
                int r0 = wr * 32 + mi * 16 + qr;
                af[mi][0] = *(uint32_t*)&sAh[r0][c0];
                af[mi][1] = *(uint32_t*)&sAh[r0 + 8][c0];
                af[mi][2] = *(uint32_t*)&sAh[r0][c0 + 8];
                af[mi][3] = *(uint32_t*)&sAh[r0 + 8][c0 + 8];
            }
            #pragma unroll
            for (int ni = 0; ni < 2; ni++) {
                int r0 = wc * 16 + ni * 8 + qr;
                bf[ni][0] = *(uint32_t*)&sBh[r0][c0];
                bf[ni][1] = *(uint32_t*)&sBh[r0][c0 + 8];
            }
            #pragma unroll
            for (int mi = 0; mi < 2; mi++)
                #pragma unroll
                for (int ni = 0; ni < 2; ni++)
                    MMA_BF16(acc[mi][ni], af[mi], bf[ni]);

            // pass 2: Ah * Wl (reuse af)
            #pragma unroll
            for (int ni = 0; ni < 2; ni++) {
                int r0 = wc * 16 + ni * 8 + qr;
                bf[ni][0] = *(uint32_t*)&sBl[r0][c0];
                bf[ni][1] = *(uint32_t*)&sBl[r0][c0 + 8];
            }
            #pragma unroll
            for (int mi = 0; mi < 2; mi++)
                #pragma unroll
                for (int ni = 0; ni < 2; ni++)
                    MMA_BF16(acc[mi][ni], af[mi], bf[ni]);

            // pass 3: Al * Wh
            #pragma unroll
            for (int mi = 0; mi < 2; mi++) {
                int r0 = wr * 32 + mi * 16 + qr;
                af[mi][0] = *(uint32_t*)&sAl[r0][c0];
                af[mi][1] = *(uint32_t*)&sAl[r0 + 8][c0];
                af[mi][2] = *(uint32_t*)&sAl[r0][c0 + 8];
                af[mi][3] = *(uint32_t*)&sAl[r0 + 8][c0 + 8];
            }
            #pragma unroll
            for (int ni = 0; ni < 2; ni++) {
                int r0 = wc * 16 + ni * 8 + qr;
                bf[ni][0] = *(uint32_t*)&sBh[r0][c0];
                bf[ni][1] = *(uint32_t*)&sBh[r0][c0 + 8];
            }
            #pragma unroll
            for (int mi = 0; mi < 2; mi++)
                #pragma unroll
                for (int ni = 0; ni < 2; ni++)
                    MMA_BF16(acc[mi][ni], af[mi], bf[ni]);
        }
        __syncthreads();
    }

    // Epilogue: C frag layout: rows lane/4 (+8), cols (lane%4)*2, +1
    #pragma unroll
    for (int mi = 0; mi < 2; mi++) {
        #pragma unroll
        for (int half = 0; half < 2; half++) {
            int m = arow0 + wr * 32 + mi * 16 + qr + half * 8;
            int b = m / S, s = m - b * S;
            #pragma unroll
            for (int ni = 0; ni < 2; ni++) {
                int n = bcol0 + wc * 16 + ni * 8 + qc * 2;   // even
                float o1 = acc[mi][ni][half * 2 + 0];
                float o2 = acc[mi][ni][half * 2 + 1];
                if (MODE == 3) {
                    g_proj[(size_t)m * DM + n]     = o1;
                    g_proj[(size_t)m * DM + n + 1] = o2;
                } else {
                    int h = n >> 6, d0 = n & 63;
                    size_t base = ((size_t)(b * NH + h) * S + s) * DH + d0;
                    if (MODE == 0) {
                        g_V[base]     = o1;
                        g_V[base + 1] = o2;
                    } else {
                        int ti = s * 32 + (d0 >> 1);
                        float co = g_rc[ti], sn = g_rs[ti];
                        float r1 = o1 * co - o2 * sn;
                        float r2 = o2 * co + o1 * sn;
                        if (MODE == 1) { r1 *= 0.125f; r2 *= 0.125f; }
                        float* outp = (MODE == 1) ? g_Q : g_K;
                        outp[base]     = r1;
                        outp[base + 1] = r2;
                    }
                }
            }
        }
    }
}

// ---------------------------------------------------------------------------
// Flash attention (R2-validated version). Grid (Sq/64, B*H), block 256.
// ---------------------------------------------------------------------------
__global__ __launch_bounds__(256)
void flash_k(const unsigned int* __restrict__ mask) {
    __shared__ float Qs[64][65];
    __shared__ float Ks[32][65];
    __shared__ float Vs[32][65];
    __shared__ float Ps[64][33];
    __shared__ float m_s[64], l_s[64], al_s[64];
    __shared__ unsigned int mk[32];

    int tid = threadIdx.x;
    int tx = tid & 15, ty = tid >> 4;
    int q0 = blockIdx.x * 64;
    int bh = blockIdx.y;
    int b  = bh >> 4;
    int h  = bh & 15;

    const float* Qg = g_Q + ((size_t)bh * SQ + q0) * DH;
    const float* Kg = g_K + (size_t)bh * SKV * DH;
    const float* Vg = g_V + (size_t)bh * SKV * DH;

    for (int e = tid; e < 64 * 64; e += 256) Qs[e >> 6][e & 63] = Qg[e];
    if (tid < 64) { m_s[tid] = -INFINITY; l_s[tid] = 0.f; }

    float O[4][4];
    #pragma unroll
    for (int i = 0; i < 4; i++)
        #pragma unroll
        for (int j = 0; j < 4; j++) O[i][j] = 0.f;

    __syncthreads();

    for (int kc = 0; kc < SKV; kc += 32) {
        for (int e = tid; e < 32 * 64; e += 256) {
            Ks[e >> 6][e & 63] = Kg[kc * 64 + e];
            Vs[e >> 6][e & 63] = Vg[kc * 64 + e];
        }
        if (tid < 32) mk[tid] = mask[b * SKV + kc + tid];
        __syncthreads();

        float sv[4][2];
        #pragma unroll
        for (int i = 0; i < 4; i++) { sv[i][0] = 0.f; sv[i][1] = 0.f; }
        #pragma unroll 8
        for (int d = 0; d < 64; d++) {
            float k0 = Ks[tx * 2 + 0][d];
            float k1 = Ks[tx * 2 + 1][d];
            #pragma unroll
            for (int i = 0; i < 4; i++) {
                float q = Qs[ty * 4 + i][d];
                sv[i][0] = fmaf(q, k0, sv[i][0]);
                sv[i][1] = fmaf(q, k1, sv[i][1]);
            }
        }
        bool ok0 = mk[tx * 2 + 0] != 0u;
        bool ok1 = mk[tx * 2 + 1] != 0u;
        #pragma unroll
        for (int i = 0; i < 4; i++) {
            Ps[ty * 4 + i][tx * 2 + 0] = ok0 ? sv[i][0] : -1000000000.0f;
            Ps[ty * 4 + i][tx * 2 + 1] = ok1 ? sv[i][1] : -1000000000.0f;
        }
        __syncthreads();

        if (tid < 64) {
            int r = tid;
            float mold = m_s[r], mx = mold;
            #pragma unroll 8
            for (int c = 0; c < 32; c++) mx = fmaxf(mx, Ps[r][c]);
            float al = expf(mold - mx);
            float sum = 0.f;
            #pragma unroll 8
            for (int c = 0; c < 32; c++) {
                float p = expf(Ps[r][c] - mx);
                Ps[r][c] = p;
                sum += p;
            }
            m_s[r]  = mx;
            al_s[r] = al;
            l_s[r]  = l_s[r] * al + sum;
        }
        __syncthreads();

        #pragma unroll
        for (int i = 0; i < 4; i++) {
            float al = al_s[ty * 4 + i];
            #pragma unroll
            for (int j = 0; j < 4; j++) O[i][j] *= al;
        }
        #pragma unroll 8
        for (int k = 0; k < 32; k++) {
            float v[4];
            #pragma unroll
            for (int j = 0; j < 4; j++) v[j] = Vs[k][tx * 4 + j];
            #pragma unroll
            for (int i = 0; i < 4; i++) {
                float p = Ps[ty * 4 + i][k];
                #pragma unroll
                for (int j = 0; j < 4; j++) O[i][j] = fmaf(p, v[j], O[i][j]);
            }
        }
        __syncthreads();
    }

    #pragma unroll
    for (int i = 0; i < 4; i++) {
        int r = ty * 4 + i;
        float invl = 1.0f / l_s[r];
        #pragma unroll
        for (int j = 0; j < 4; j++)
            g_ctx[((size_t)b * SQ + q0 + r) * DM + h * 64 + tx * 4 + j] = O[i][j] * invl;
    }
}

// ---------------------------------------------------------------------------
// Residual + LayerNorm, one block per row.
// ---------------------------------------------------------------------------
__global__ __launch_bounds__(256)
void ln_k(const float* __restrict__ dq, const float* __restrict__ gamma,
          const float* __restrict__ beta, float* __restrict__ out) {
    int row = blockIdx.x;
    int tid = threadIdx.x;
    __shared__ float red[256];
    __shared__ float mu_s, var_s;

    float x[4];
    float s = 0.f;
    #pragma unroll
    for (int u = 0; u < 4; u++) {
        int idx = u * 256 + tid;
        x[u] = dq[(size_t)row * DM + idx] + g_proj[(size_t)row * DM + idx];
        s += x[u];
    }
    red[tid] = s;
    __syncthreads();
    for (int st = 128; st > 0; st >>= 1) {
        if (tid < st) red[tid] += red[tid + st];
        __syncthreads();
    }
    if (tid == 0) mu_s = red[0] * (1.0f / DM);
    __syncthreads();
    float mu = mu_s;

    s = 0.f;
    #pragma unroll
    for (int u = 0; u < 4; u++) {
        float d2 = x[u] - mu;
        s += d2 * d2;
    }
    red[tid] = s;
    __syncthreads();
    for (int st = 128; st > 0; st >>= 1) {
        if (tid < st) red[tid] += red[tid + st];
        __syncthreads();
    }
    if (tid == 0) var_s = red[0] * (1.0f / DM);
    __syncthreads();
    float rstd = rsqrtf(var_s + 0.001f);

    #pragma unroll
    for (int u = 0; u < 4; u++) {
        int idx = u * 256 + tid;
        out[(size_t)row * DM + idx] = (x[u] - mu) * rstd * gamma[idx] + beta[idx];
    }
}

// ---------------------------------------------------------------------------
extern "C" void kernel_launch(void* const* d_in, const int* in_sizes, int n_in,
                              void* d_out, int out_size) {
    const float* dq    = (const float*)d_in[0];
    const float* ekv   = (const float*)d_in[1];
    const unsigned int* mask = (const unsigned int*)d_in[2];
    const float* Wq    = (const float*)d_in[3];
    const float* Wk    = (const float*)d_in[4];
    const float* Wv    = (const float*)d_in[5];
    const float* Wo    = (const float*)d_in[6];
    const float* gamma = (const float*)d_in[7];
    const float* beta  = (const float*)d_in[8];
    float* out = (float*)d_out;

    // RoPE cos/sin table
    rope_table_k<<<(SKV * 32 + 255) / 256, 256>>>();

    // Projections (tensor cores via mma.sync, on-the-fly bf16 split) + RoPE
    mgemm_k<1><<<dim3(16, 64), 256>>>(dq,  Wq, SQ);
    mgemm_k<2><<<dim3(16, 128), 256>>>(ekv, Wk, SKV);
    mgemm_k<0><<<dim3(16, 128), 256>>>(ekv, Wv, SKV);

    // Attention
    flash_k<<<dim3(SQ / 64, Bb * NH), 256>>>(mask);

    // Output projection (A = g_ctx selected inside kernel via MODE)
    mgemm_k<3><<<dim3(16, 64), 256>>>(nullptr, Wo, SQ);

    // Residual + LayerNorm
    ln_k<<<Bb * SQ, 256>>>(dq, gamma, beta, out);
}

// round 9
// speedup vs baseline: 1.2921x; 1.2921x over previous
#include <cuda_runtime.h>
#include <cuda_bf16.h>
#include <math.h>
#include <stdint.h>

#define Bb 4
#define SQ 1024
#define SKV 2048
#define DM 1024
#define NH 16
#define DH 64

// ---------------------------------------------------------------------------
// Scratch (device globals; statically allocated, referenced ONLY in device
// code — never passed as kernel arguments from host (R5-R7 failure mode)).
// ---------------------------------------------------------------------------
__device__ __align__(16) float g_Q[Bb*NH*SQ*DH];     // [B,H,Sq,Dh] (rope'd, scaled)
__device__ __align__(16) float g_K[Bb*NH*SKV*DH];    // [B,H,Skv,Dh] (rope'd)
__device__ __align__(16) float g_V[Bb*NH*SKV*DH];    // [B,H,Skv,Dh]
__device__ __align__(16) float g_ctx[Bb*SQ*DM];      // [B,Sq,H*Dh]
__device__ __align__(16) float g_proj[Bb*SQ*DM];     // [B,Sq,DM]
__device__ __align__(16) float g_rc[SKV*32];         // rope cos [s][pair]
__device__ __align__(16) float g_rs[SKV*32];         // rope sin [s][pair]
// transposed [N,K] bf16 weight splits: 0=Wq 1=Wk 2=Wv 3=Wo
__device__ __align__(16) __nv_bfloat16 g_Wth[4][DM*DM];
__device__ __align__(16) __nv_bfloat16 g_Wtl[4][DM*DM];

// ---------------------------------------------------------------------------
// mma.sync bf16: D(16x8) += A(16x16,row) * B(16x8,col), fp32 accum
// ---------------------------------------------------------------------------
#define MMA_BF16(d, a, b) \
    asm volatile("mma.sync.aligned.m16n8k16.row.col.f32.bf16.bf16.f32 " \
        "{%0,%1,%2,%3}, {%4,%5,%6,%7}, {%8,%9}, {%0,%1,%2,%3};" \
        : "+f"((d)[0]), "+f"((d)[1]), "+f"((d)[2]), "+f"((d)[3]) \
        : "r"((a)[0]), "r"((a)[1]), "r"((a)[2]), "r"((a)[3]), \
          "r"((b)[0]), "r"((b)[1]))

// ---------------------------------------------------------------------------
// Prep
// ---------------------------------------------------------------------------
__global__ void rope_table_k() {
    int idx = blockIdx.x * blockDim.x + threadIdx.x;
    if (idx >= SKV * 32) return;
    int s = idx >> 5, p = idx & 31;
    double inv = pow(10000.0, -(double)(2 * p) / 64.0);
    double ang = (double)s * inv;
    g_rc[idx] = (float)cos(ang);
    g_rs[idx] = (float)sin(ang);
}

__device__ __forceinline__ void split2(float a, float b, uint32_t& hp, uint32_t& lp) {
    __nv_bfloat16 ha = __float2bfloat16(a), hb = __float2bfloat16(b);
    float la = a - __bfloat162float(ha);
    float lb = b - __bfloat162float(hb);
    __nv_bfloat16 hla = __float2bfloat16(la), hlb = __float2bfloat16(lb);
    hp = (uint32_t)__bfloat16_as_ushort(ha) | ((uint32_t)__bfloat16_as_ushort(hb) << 16);
    lp = (uint32_t)__bfloat16_as_ushort(hla) | ((uint32_t)__bfloat16_as_ushort(hlb) << 16);
}

// transpose + split: g_Wth[WIDX][n*DM+k] = bf16hi(W[k*DM+n]); g_Wtl = residual
template<int WIDX>
__global__ void tsplit_k(const float* __restrict__ W) {
    __shared__ float t[32][33];
    int n0 = blockIdx.x * 32, k0 = blockIdx.y * 32;
    int tx = threadIdx.x, ty = threadIdx.y;    // 32 x 8
    #pragma unroll
    for (int r = 0; r < 32; r += 8)
        t[ty + r][tx] = W[(k0 + ty + r) * DM + n0 + tx];
    __syncthreads();
    __nv_bfloat16* Th = g_Wth[WIDX];
    __nv_bfloat16* Tl = g_Wtl[WIDX];
    #pragma unroll
    for (int r = 0; r < 32; r += 8) {
        float v = t[tx][ty + r];   // = W[k0+tx][n0+ty+r]
        __nv_bfloat16 hh = __float2bfloat16(v);
        int o = (n0 + ty + r) * DM + k0 + tx;
        Th[o] = hh;
        Tl[o] = __float2bfloat16(v - __bfloat162float(hh));
    }
}

// ---------------------------------------------------------------------------
// mma.sync GEMM: C[M,1024] = A[M,1024] @ W[1024,1024]
// A fp32 split on the fly; W pre-split in g_Wth/g_Wtl (selected by WIDX).
// 3-term: Ah*Wh + Ah*Wl + Al*Wh, fp32 accum (~2^-16 rel accuracy).
// Tile 128x128, KC=32, 8 warps (2x4), warp tile 64x32 = 4x4 m16n8k16 frags.
// MODE 0: V   MODE 1: Q (rope + 0.125)   MODE 2: K (rope)   MODE 3: proj
// ---------------------------------------------------------------------------
#define KC   32
#define TSTR 40   // 80B rows: conflict-free fragment loads (R8-validated)

template<int MODE, int WIDX>
__global__ __launch_bounds__(256)
void mgemm_k(const float* __restrict__ A, int S) {
    __shared__ __align__(16) __nv_bfloat16 sAh[128][TSTR], sAl[128][TSTR];
    __shared__ __align__(16) __nv_bfloat16 sBh[128][TSTR], sBl[128][TSTR];

    const float* Ain = (MODE == 3) ? g_ctx : A;
    const __nv_bfloat16* Wh = g_Wth[WIDX];
    const __nv_bfloat16* Wl = g_Wtl[WIDX];

    int tid = threadIdx.x, wid = tid >> 5, lane = tid & 31;
    int wr = wid >> 2, wc = wid & 3;          // 2 x 4 warp grid
    int qr = lane >> 2, qc = lane & 3;        // quad row/col
    const int arow0 = blockIdx.y * 128, bcol0 = blockIdx.x * 128;

    float acc[4][4][4];
    #pragma unroll
    for (int mi = 0; mi < 4; mi++)
        #pragma unroll
        for (int ni = 0; ni < 4; ni++)
            #pragma unroll
            for (int e = 0; e < 4; e++) acc[mi][ni][e] = 0.f;

    for (int kt = 0; kt < DM; kt += KC) {
        // stage A [128][32] fp32 -> split bf16 h/l (2 vectors/thread)
        #pragma unroll
        for (int v = 0; v < 2; v++) {
            int lin = tid + 256 * v;
            int r = lin >> 2, c = (lin & 3) * 8;
            const float* src = Ain + (size_t)(arow0 + r) * DM + kt + c;
            float vv[8];
            *(float4*)(vv)     = *(const float4*)(src);
            *(float4*)(vv + 4) = *(const float4*)(src + 4);
            uint32_t hp[4], lp[4];
            #pragma unroll
            for (int i = 0; i < 4; i++) split2(vv[2*i], vv[2*i+1], hp[i], lp[i]);
            *(uint4*)&sAh[r][c] = *(uint4*)hp;
            *(uint4*)&sAl[r][c] = *(uint4*)lp;
        }
        // stage W [128 n][32 k] bf16 h/l: pure vector copies (2/thread each)
        #pragma unroll
        for (int v = 0; v < 2; v++) {
            int lin = tid + 256 * v;
            int r = lin >> 2, c = (lin & 3) * 8;
            size_t go = (size_t)(bcol0 + r) * DM + kt + c;
            *(uint4*)&sBh[r][c] = *(const uint4*)(Wh + go);
            *(uint4*)&sBl[r][c] = *(const uint4*)(Wl + go);
        }
        __syncthreads();

        #pragma unroll
        for (int k16 = 0; k16 < KC; k16 += 16) {
            int c0 = k16 + qc * 2;
            uint32_t af[4][4], bf[4][2];

            // pass 1: Ah * Wh
            #pragma unroll
            for (int mi = 0; mi < 4; mi++) {
                int r0 = wr * 64 + mi * 16 + qr;
                af[mi][0] = *(uint32_t*)&sAh[r0][c0];
                af[mi][1] = *(uint32_t*)&sAh[r0 + 8][c0];
                af[mi][2] = *(uint32_t*)&sAh[r0][c0 + 8];
                af[mi][3] = *(uint32_t*)&sAh[r0 + 8][c0 + 8];
            }
            #pragma unroll
            for (int ni = 0; ni < 4; ni++) {
                int r0 = wc * 32 + ni * 8 + qr;
                bf[ni][0] = *(uint32_t*)&sBh[r0][c0];
                bf[ni][1] = *(uint32_t*)&sBh[r0][c0 + 8];
            }
            #pragma unroll
            for (int mi = 0; mi < 4; mi++)
                #pragma unroll
                for (int ni = 0; ni < 4; ni++)
                    MMA_BF16(acc[mi][ni], af[mi], bf[ni]);

            // pass 2: Ah * Wl (reuse af)
            #pragma unroll
            for (int ni = 0; ni < 4; ni++) {
                int r0 = wc * 32 + ni * 8 + qr;
                bf[ni][0] = *(uint32_t*)&sBl[r0][c0];
                bf[ni][1] = *(uint32_t*)&sBl[r0][c0 + 8];
            }
            #pragma unroll
            for (int mi = 0; mi < 4; mi++)
                #pragma unroll
                for (int ni = 0; ni < 4; ni++)
                    MMA_BF16(acc[mi][ni], af[mi], bf[ni]);

            // pass 3: Al * Wh
            #pragma unroll
            for (int mi = 0; mi < 4; mi++) {
                int r0 = wr * 64 + mi * 16 + qr;
                af[mi][0] = *(uint32_t*)&sAl[r0][c0];
                af[mi][1] = *(uint32_t*)&sAl[r0 + 8][c0];
                af[mi][2] = *(uint32_t*)&sAl[r0][c0 + 8];
                af[mi][3] = *(uint32_t*)&sAl[r0 + 8][c0 + 8];
            }
            #pragma unroll
            for (int ni = 0; ni < 4; ni++) {
                int r0 = wc * 32 + ni * 8 + qr;
                bf[ni][0] = *(uint32_t*)&sBh[r0][c0];
                bf[ni][1] = *(uint32_t*)&sBh[r0][c0 + 8];
            }
            #pragma unroll
            for (int mi = 0; mi < 4; mi++)
                #pragma unroll
                for (int ni = 0; ni < 4; ni++)
                    MMA_BF16(acc[mi][ni], af[mi], bf[ni]);
        }
        __syncthreads();
    }

    // Epilogue: C frag layout: rows lane/4 (+8), cols (lane%4)*2, +1
    #pragma unroll
    for (int mi = 0; mi < 4; mi++) {
        #pragma unroll
        for (int half = 0; half < 2; half++) {
            int m = arow0 + wr * 64 + mi * 16 + qr + half * 8;
            int b = m / S, s = m - b * S;
            #pragma unroll
            for (int ni = 0; ni < 4; ni++) {
                int n = bcol0 + wc * 32 + ni * 8 + qc * 2;   // even
                float o1 = acc[mi][ni][half * 2 + 0];
                float o2 = acc[mi][ni][half * 2 + 1];
                if (MODE == 3) {
                    g_proj[(size_t)m * DM + n]     = o1;
                    g_proj[(size_t)m * DM + n + 1] = o2;
                } else {
                    int h = n >> 6, d0 = n & 63;
                    size_t base = ((size_t)(b * NH + h) * S + s) * DH + d0;
                    if (MODE == 0) {
                        g_V[base]     = o1;
                        g_V[base + 1] = o2;
                    } else {
                        int ti = s * 32 + (d0 >> 1);
                        float co = g_rc[ti], sn = g_rs[ti];
                        float r1 = o1 * co - o2 * sn;
                        float r2 = o2 * co + o1 * sn;
                        if (MODE == 1) { r1 *= 0.125f; r2 *= 0.125f; }
                        float* outp = (MODE == 1) ? g_Q : g_K;
                        outp[base]     = r1;
                        outp[base + 1] = r2;
                    }
                }
            }
        }
    }
}

// ---------------------------------------------------------------------------
// Flash attention (R2-validated). Grid (Sq/64, B*H), block 256.
// ---------------------------------------------------------------------------
__global__ __launch_bounds__(256)
void flash_k(const unsigned int* __restrict__ mask) {
    __shared__ float Qs[64][65];
    __shared__ float Ks[32][65];
    __shared__ float Vs[32][65];
    __shared__ float Ps[64][33];
    __shared__ float m_s[64], l_s[64], al_s[64];
    __shared__ unsigned int mk[32];

    int tid = threadIdx.x;
    int tx = tid & 15, ty = tid >> 4;
    int q0 = blockIdx.x * 64;
    int bh = blockIdx.y;
    int b  = bh >> 4;
    int h  = bh & 15;

    const float* Qg = g_Q + ((size_t)bh * SQ + q0) * DH;
    const float* Kg = g_K + (size_t)bh * SKV * DH;
    const float* Vg = g_V + (size_t)bh * SKV * DH;

    for (int e = tid; e < 64 * 64; e += 256) Qs[e >> 6][e & 63] = Qg[e];
    if (tid < 64) { m_s[tid] = -INFINITY; l_s[tid] = 0.f; }

    float O[4][4];
    #pragma unroll
    for (int i = 0; i < 4; i++)
        #pragma unroll
        for (int j = 0; j < 4; j++) O[i][j] = 0.f;

    __syncthreads();

    for (int kc = 0; kc < SKV; kc += 32) {
        for (int e = tid; e < 32 * 64; e += 256) {
            Ks[e >> 6][e & 63] = Kg[kc * 64 + e];
            Vs[e >> 6][e & 63] = Vg[kc * 64 + e];
        }
        if (tid < 32) mk[tid] = mask[b * SKV + kc + tid];
        __syncthreads();

        float sv[4][2];
        #pragma unroll
        for (int i = 0; i < 4; i++) { sv[i][0] = 0.f; sv[i][1] = 0.f; }
        #pragma unroll 8
        for (int d = 0; d < 64; d++) {
            float k0 = Ks[tx * 2 + 0][d];
            float k1 = Ks[tx * 2 + 1][d];
            #pragma unroll
            for (int i = 0; i < 4; i++) {
                float q = Qs[ty * 4 + i][d];
                sv[i][0] = fmaf(q, k0, sv[i][0]);
                sv[i][1] = fmaf(q, k1, sv[i][1]);
            }
        }
        bool ok0 = mk[tx * 2 + 0] != 0u;
        bool ok1 = mk[tx * 2 + 1] != 0u;
        #pragma unroll
        for (int i = 0; i < 4; i++) {
            Ps[ty * 4 + i][tx * 2 + 0] = ok0 ? sv[i][0] : -1000000000.0f;
            Ps[ty * 4 + i][tx * 2 + 1] = ok1 ? sv[i][1] : -1000000000.0f;
        }
        __syncthreads();

        if (tid < 64) {
            int r = tid;
            float mold = m_s[r], mx = mold;
            #pragma unroll 8
            for (int c = 0; c < 32; c++) mx = fmaxf(mx, Ps[r][c]);
            float al = expf(mold - mx);
            float sum = 0.f;
            #pragma unroll 8
            for (int c = 0; c < 32; c++) {
                float p = expf(Ps[r][c] - mx);
                Ps[r][c] = p;
                sum += p;
            }
            m_s[r]  = mx;
            al_s[r] = al;
            l_s[r]  = l_s[r] * al + sum;
        }
        __syncthreads();

        #pragma unroll
        for (int i = 0; i < 4; i++) {
            float al = al_s[ty * 4 + i];
            #pragma unroll
            for (int j = 0; j < 4; j++) O[i][j] *= al;
        }
        #pragma unroll 8
        for (int k = 0; k < 32; k++) {
            float v[4];
            #pragma unroll
            for (int j = 0; j < 4; j++) v[j] = Vs[k][tx * 4 + j];
            #pragma unroll
            for (int i = 0; i < 4; i++) {
                float p = Ps[ty * 4 + i][k];
                #pragma unroll
                for (int j = 0; j < 4; j++) O[i][j] = fmaf(p, v[j], O[i][j]);
            }
        }
        __syncthreads();
    }

    #pragma unroll
    for (int i = 0; i < 4; i++) {
        int r = ty * 4 + i;
        float invl = 1.0f / l_s[r];
        #pragma unroll
        for (int j = 0; j < 4; j++)
            g_ctx[((size_t)b * SQ + q0 + r) * DM + h * 64 + tx * 4 + j] = O[i][j] * invl;
    }
}

// ---------------------------------------------------------------------------
// Residual + LayerNorm, one block per row.
// ---------------------------------------------------------------------------
__global__ __launch_bounds__(256)
void ln_k(const float* __restrict__ dq, const float* __restrict__ gamma,
          const float* __restrict__ beta, float* __restrict__ out) {
    int row = blockIdx.x;
    int tid = threadIdx.x;
    __shared__ float red[256];
    __shared__ float mu_s, var_s;

    float x[4];
    float s = 0.f;
    #pragma unroll
    for (int u = 0; u < 4; u++) {
        int idx = u * 256 + tid;
        x[u] = dq[(size_t)row * DM + idx] + g_proj[(size_t)row * DM + idx];
        s += x[u];
    }
    red[tid] = s;
    __syncthreads();
    for (int st = 128; st > 0; st >>= 1) {
        if (tid < st) red[tid] += red[tid + st];
        __syncthreads();
    }
    if (tid == 0) mu_s = red[0] * (1.0f / DM);
    __syncthreads();
    float mu = mu_s;

    s = 0.f;
    #pragma unroll
    for (int u = 0; u < 4; u++) {
        float d2 = x[u] - mu;
        s += d2 * d2;
    }
    red[tid] = s;
    __syncthreads();
    for (int st = 128; st > 0; st >>= 1) {
        if (tid < st) red[tid] += red[tid + st];
        __syncthreads();
    }
    if (tid == 0) var_s = red[0] * (1.0f / DM);
    __syncthreads();
    float rstd = rsqrtf(var_s + 0.001f);

    #pragma unroll
    for (int u = 0; u < 4; u++) {
        int idx = u * 256 + tid;
        out[(size_t)row * DM + idx] = (x[u] - mu) * rstd * gamma[idx] + beta[idx];
    }
}

// ---------------------------------------------------------------------------
extern "C" void kernel_launch(void* const* d_in, const int* in_sizes, int n_in,
                              void* d_out, int out_size) {
    const float* dq    = (const float*)d_in[0];
    const float* ekv   = (const float*)d_in[1];
    const unsigned int* mask = (const unsigned int*)d_in[2];
    const float* Wq    = (const float*)d_in[3];
    const float* Wk    = (const float*)d_in[4];
    const float* Wv    = (const float*)d_in[5];
    const float* Wo    = (const float*)d_in[6];
    const float* gamma = (const float*)d_in[7];
    const float* beta  = (const float*)d_in[8];
    float* out = (float*)d_out;

    // Prep: rope table + weight transpose/split (harness pointers in,
    // internal globals out — no device-symbol kernel args)
    rope_table_k<<<(SKV * 32 + 255) / 256, 256>>>();
    tsplit_k<0><<<dim3(32, 32), dim3(32, 8)>>>(Wq);
    tsplit_k<1><<<dim3(32, 32), dim3(32, 8)>>>(Wk);
    tsplit_k<2><<<dim3(32, 32), dim3(32, 8)>>>(Wv);
    tsplit_k<3><<<dim3(32, 32), dim3(32, 8)>>>(Wo);

    // Projections (mma.sync, 128x128 tiles) + fused RoPE
    mgemm_k<1, 0><<<dim3(8, 32), 256>>>(dq,  SQ);
    mgemm_k<2, 1><<<dim3(8, 64), 256>>>(ekv, SKV);
    mgemm_k<0, 2><<<dim3(8, 64), 256>>>(ekv, SKV);

    // Attention
    flash_k<<<dim3(SQ / 64, Bb * NH), 256>>>(mask);

    // Output projection (A = g_ctx selected inside kernel via MODE)
    mgemm_k<3, 3><<<dim3(8, 32), 256>>>(nullptr, SQ);

    // Residual + LayerNorm
    ln_k<<<Bb * SQ, 256>>>(dq, gamma, beta, out);
}

// round 10
// speedup vs baseline: 2.0541x; 1.5897x over previous
#include <cuda_runtime.h>
#include <cuda_bf16.h>
#include <math.h>
#include <stdint.h>

#define Bb 4
#define SQ 1024
#define SKV 2048
#define DM 1024
#define NH 16
#define DH 64

// ---------------------------------------------------------------------------
// Scratch (device globals; referenced ONLY inside device code — never passed
// as kernel args from host). ~128.5 MB total.
// ---------------------------------------------------------------------------
__device__ __align__(16) float g_ctx[Bb*SQ*DM];      // [B,Sq,H*Dh]
__device__ __align__(16) float g_proj[Bb*SQ*DM];     // [B,Sq,DM]
__device__ __align__(16) float g_rc[SKV*32];         // rope cos [s][pair]
__device__ __align__(16) float g_rs[SKV*32];         // rope sin [s][pair]
// transposed [N,K] bf16 weight splits: 0=Wq 1=Wk 2=Wv 3=Wo
__device__ __align__(16) __nv_bfloat16 g_Wth[4][DM*DM];
__device__ __align__(16) __nv_bfloat16 g_Wtl[4][DM*DM];
// attention operands, bf16 hi/lo splits
__device__ __align__(16) __nv_bfloat16 g_Qbh[Bb*NH*SQ*DH],  g_Qbl[Bb*NH*SQ*DH];   // [b,h,s,d]
__device__ __align__(16) __nv_bfloat16 g_Kbh[Bb*NH*SKV*DH], g_Kbl[Bb*NH*SKV*DH];  // [b,h,s,d]
__device__ __align__(16) __nv_bfloat16 g_VTh[Bb*NH*DH*SKV], g_VTl[Bb*NH*DH*SKV];  // [b,h,d,s]

// ---------------------------------------------------------------------------
// mma.sync bf16: D(16x8) += A(16x16,row) * B(16x8,col), fp32 accum
// ---------------------------------------------------------------------------
#define MMA_BF16(d, a, b) \
    asm volatile("mma.sync.aligned.m16n8k16.row.col.f32.bf16.bf16.f32 " \
        "{%0,%1,%2,%3}, {%4,%5,%6,%7}, {%8,%9}, {%0,%1,%2,%3};" \
        : "+f"((d)[0]), "+f"((d)[1]), "+f"((d)[2]), "+f"((d)[3]) \
        : "r"((a)[0]), "r"((a)[1]), "r"((a)[2]), "r"((a)[3]), \
          "r"((b)[0]), "r"((b)[1]))

__device__ __forceinline__ void split2(float a, float b, uint32_t& hp, uint32_t& lp) {
    __nv_bfloat16 ha = __float2bfloat16(a), hb = __float2bfloat16(b);
    float la = a - __bfloat162float(ha);
    float lb = b - __bfloat162float(hb);
    __nv_bfloat16 hla = __float2bfloat16(la), hlb = __float2bfloat16(lb);
    hp = (uint32_t)__bfloat16_as_ushort(ha) | ((uint32_t)__bfloat16_as_ushort(hb) << 16);
    lp = (uint32_t)__bfloat16_as_ushort(hla) | ((uint32_t)__bfloat16_as_ushort(hlb) << 16);
}

// ---------------------------------------------------------------------------
// Prep
// ---------------------------------------------------------------------------
__global__ void rope_table_k() {
    int idx = blockIdx.x * blockDim.x + threadIdx.x;
    if (idx >= SKV * 32) return;
    int s = idx >> 5, p = idx & 31;
    double inv = pow(10000.0, -(double)(2 * p) / 64.0);
    double ang = (double)s * inv;
    g_rc[idx] = (float)cos(ang);
    g_rs[idx] = (float)sin(ang);
}

template<int WIDX>
__global__ void tsplit_k(const float* __restrict__ W) {
    __shared__ float t[32][33];
    int n0 = blockIdx.x * 32, k0 = blockIdx.y * 32;
    int tx = threadIdx.x, ty = threadIdx.y;    // 32 x 8
    #pragma unroll
    for (int r = 0; r < 32; r += 8)
        t[ty + r][tx] = W[(k0 + ty + r) * DM + n0 + tx];
    __syncthreads();
    __nv_bfloat16* Th = g_Wth[WIDX];
    __nv_bfloat16* Tl = g_Wtl[WIDX];
    #pragma unroll
    for (int r = 0; r < 32; r += 8) {
        float v = t[tx][ty + r];
        __nv_bfloat16 hh = __float2bfloat16(v);
        int o = (n0 + ty + r) * DM + k0 + tx;
        Th[o] = hh;
        Tl[o] = __float2bfloat16(v - __bfloat162float(hh));
    }
}

// ---------------------------------------------------------------------------
// mma.sync GEMM (R9-validated core). MODE 0: V -> g_VT h/l (transposed bf16)
// MODE 1: Q (rope+0.125) -> g_Qb h/l    MODE 2: K (rope) -> g_Kb h/l
// MODE 3: g_ctx @ Wo -> g_proj (fp32)
// ---------------------------------------------------------------------------
#define KC   32
#define TSTR 40

template<int MODE, int WIDX>
__global__ __launch_bounds__(256)
void mgemm_k(const float* __restrict__ A, int S) {
    __shared__ __align__(16) __nv_bfloat16 sAh[128][TSTR], sAl[128][TSTR];
    __shared__ __align__(16) __nv_bfloat16 sBh[128][TSTR], sBl[128][TSTR];

    const float* Ain = (MODE == 3) ? g_ctx : A;
    const __nv_bfloat16* Wh = g_Wth[WIDX];
    const __nv_bfloat16* Wl = g_Wtl[WIDX];

    int tid = threadIdx.x, wid = tid >> 5, lane = tid & 31;
    int wr = wid >> 2, wc = wid & 3;
    int qr = lane >> 2, qc = lane & 3;
    const int arow0 = blockIdx.y * 128, bcol0 = blockIdx.x * 128;

    float acc[4][4][4];
    #pragma unroll
    for (int mi = 0; mi < 4; mi++)
        #pragma unroll
        for (int ni = 0; ni < 4; ni++)
            #pragma unroll
            for (int e = 0; e < 4; e++) acc[mi][ni][e] = 0.f;

    for (int kt = 0; kt < DM; kt += KC) {
        #pragma unroll
        for (int v = 0; v < 2; v++) {
            int lin = tid + 256 * v;
            int r = lin >> 2, c = (lin & 3) * 8;
            const float* src = Ain + (size_t)(arow0 + r) * DM + kt + c;
            float vv[8];
            *(float4*)(vv)     = *(const float4*)(src);
            *(float4*)(vv + 4) = *(const float4*)(src + 4);
            uint32_t hp[4], lp[4];
            #pragma unroll
            for (int i = 0; i < 4; i++) split2(vv[2*i], vv[2*i+1], hp[i], lp[i]);
            *(uint4*)&sAh[r][c] = *(uint4*)hp;
            *(uint4*)&sAl[r][c] = *(uint4*)lp;
        }
        #pragma unroll
        for (int v = 0; v < 2; v++) {
            int lin = tid + 256 * v;
            int r = lin >> 2, c = (lin & 3) * 8;
            size_t go = (size_t)(bcol0 + r) * DM + kt + c;
            *(uint4*)&sBh[r][c] = *(const uint4*)(Wh + go);
            *(uint4*)&sBl[r][c] = *(const uint4*)(Wl + go);
        }
        __syncthreads();

        #pragma unroll
        for (int k16 = 0; k16 < KC; k16 += 16) {
            int c0 = k16 + qc * 2;
            uint32_t af[4][4], bf[4][2];
            #pragma unroll
            for (int mi = 0; mi < 4; mi++) {
                int r0 = wr * 64 + mi * 16 + qr;
                af[mi][0] = *(uint32_t*)&sAh[r0][c0];
                af[mi][1] = *(uint32_t*)&sAh[r0 + 8][c0];
                af[mi][2] = *(uint32_t*)&sAh[r0][c0 + 8];
                af[mi][3] = *(uint32_t*)&sAh[r0 + 8][c0 + 8];
            }
            #pragma unroll
            for (int ni = 0; ni < 4; ni++) {
                int r0 = wc * 32 + ni * 8 + qr;
                bf[ni][0] = *(uint32_t*)&sBh[r0][c0];
                bf[ni][1] = *(uint32_t*)&sBh[r0][c0 + 8];
            }
            #pragma unroll
            for (int mi = 0; mi < 4; mi++)
                #pragma unroll
                for (int ni = 0; ni < 4; ni++)
                    MMA_BF16(acc[mi][ni], af[mi], bf[ni]);

            #pragma unroll
            for (int ni = 0; ni < 4; ni++) {
                int r0 = wc * 32 + ni * 8 + qr;
                bf[ni][0] = *(uint32_t*)&sBl[r0][c0];
                bf[ni][1] = *(uint32_t*)&sBl[r0][c0 + 8];
            }
            #pragma unroll
            for (int mi = 0; mi < 4; mi++)
                #pragma unroll
                for (int ni = 0; ni < 4; ni++)
                    MMA_BF16(acc[mi][ni], af[mi], bf[ni]);

            #pragma unroll
            for (int mi = 0; mi < 4; mi++) {
                int r0 = wr * 64 + mi * 16 + qr;
                af[mi][0] = *(uint32_t*)&sAl[r0][c0];
                af[mi][1] = *(uint32_t*)&sAl[r0 + 8][c0];
                af[mi][2] = *(uint32_t*)&sAl[r0][c0 + 8];
                af[mi][3] = *(uint32_t*)&sAl[r0 + 8][c0 + 8];
            }
            #pragma unroll
            for (int ni = 0; ni < 4; ni++) {
                int r0 = wc * 32 + ni * 8 + qr;
                bf[ni][0] = *(uint32_t*)&sBh[r0][c0];
                bf[ni][1] = *(uint32_t*)&sBh[r0][c0 + 8];
            }
            #pragma unroll
            for (int mi = 0; mi < 4; mi++)
                #pragma unroll
                for (int ni = 0; ni < 4; ni++)
                    MMA_BF16(acc[mi][ni], af[mi], bf[ni]);
        }
        __syncthreads();
    }

    // Epilogue
    #pragma unroll
    for (int mi = 0; mi < 4; mi++) {
        #pragma unroll
        for (int half = 0; half < 2; half++) {
            int m = arow0 + wr * 64 + mi * 16 + qr + half * 8;
            int bb = m / S, s = m - bb * S;
            #pragma unroll
            for (int ni = 0; ni < 4; ni++) {
                int n = bcol0 + wc * 32 + ni * 8 + qc * 2;   // even
                float o1 = acc[mi][ni][half * 2 + 0];
                float o2 = acc[mi][ni][half * 2 + 1];
                if (MODE == 3) {
                    g_proj[(size_t)m * DM + n]     = o1;
                    g_proj[(size_t)m * DM + n + 1] = o2;
                } else {
                    int hh = n >> 6, d0 = n & 63;
                    if (MODE == 0) {
                        // V: store transposed bf16 splits [b,h,d,s]
                        size_t vb = ((size_t)(bb * NH + hh) * DH) * SKV + s;
                        __nv_bfloat16 h1 = __float2bfloat16(o1);
                        __nv_bfloat16 h2 = __float2bfloat16(o2);
                        g_VTh[vb + (size_t)d0 * SKV]       = h1;
                        g_VTh[vb + (size_t)(d0 + 1) * SKV] = h2;
                        g_VTl[vb + (size_t)d0 * SKV]       = __float2bfloat16(o1 - __bfloat162float(h1));
                        g_VTl[vb + (size_t)(d0 + 1) * SKV] = __float2bfloat16(o2 - __bfloat162float(h2));
                    } else {
                        int ti = s * 32 + (d0 >> 1);
                        float co = g_rc[ti], sn = g_rs[ti];
                        float r1 = o1 * co - o2 * sn;
                        float r2 = o2 * co + o1 * sn;
                        if (MODE == 1) { r1 *= 0.125f; r2 *= 0.125f; }
                        size_t base = ((size_t)(bb * NH + hh) * S + s) * DH + d0;
                        uint32_t hp, lp;
                        split2(r1, r2, hp, lp);
                        if (MODE == 1) {
                            *(uint32_t*)&g_Qbh[base] = hp;
                            *(uint32_t*)&g_Qbl[base] = lp;
                        } else {
                            *(uint32_t*)&g_Kbh[base] = hp;
                            *(uint32_t*)&g_Kbl[base] = lp;
                        }
                    }
                }
            }
        }
    }
}

// ---------------------------------------------------------------------------
// Tensor-core flash attention. Grid (SQ/128, B*NH), 256 threads, dyn smem.
// Q tile 128 rows; KV chunk 64. Each warp: 16 rows x 64 keys (1 m-frag x 8
// n-frags) -> softmax entirely quad-local (shfl over lanes xor 1,2).
// S = QhKh+QhKl+QlKh; PV = PhVh+PhVl+PlVh (P re-split in registers).
// ---------------------------------------------------------------------------
#define TS2 72   // bf16 row stride: 36 words -> 32 distinct banks for frag loads
// smem byte offsets
#define OQH 0
#define OQL (OQH + 128*TS2*2)
#define OKH (OQL + 128*TS2*2)
#define OKL (OKH + 64*TS2*2)
#define OVH (OKL + 64*TS2*2)
#define OVL (OVH + 64*TS2*2)
#define OPEN (OVL + 64*TS2*2)
#define FSMEM (OPEN + 64*4)

__global__ __launch_bounds__(256)
void flash_k(const unsigned int* __restrict__ mask) {
    extern __shared__ __align__(16) char sm[];
    __nv_bfloat16* sQh = (__nv_bfloat16*)(sm + OQH);
    __nv_bfloat16* sQl = (__nv_bfloat16*)(sm + OQL);
    __nv_bfloat16* sKh = (__nv_bfloat16*)(sm + OKH);
    __nv_bfloat16* sKl = (__nv_bfloat16*)(sm + OKL);
    __nv_bfloat16* sVh = (__nv_bfloat16*)(sm + OVH);
    __nv_bfloat16* sVl = (__nv_bfloat16*)(sm + OVL);
    float* pen = (float*)(sm + OPEN);

    int tid = threadIdx.x, w = tid >> 5, lane = tid & 31;
    int r = lane >> 2, qc = lane & 3;
    int q0 = blockIdx.x * 128;
    int bh = blockIdx.y;
    int b = bh >> 4, h = bh & 15;
    int row0 = w * 16 + r;            // warp rows row0, row0+8

    const __nv_bfloat16* Qh = g_Qbh + (size_t)bh * SQ * DH + (size_t)q0 * DH;
    const __nv_bfloat16* Ql = g_Qbl + (size_t)bh * SQ * DH + (size_t)q0 * DH;
    const __nv_bfloat16* Kh = g_Kbh + (size_t)bh * SKV * DH;
    const __nv_bfloat16* Kl = g_Kbl + (size_t)bh * SKV * DH;
    const __nv_bfloat16* Vh = g_VTh + (size_t)bh * DH * SKV;
    const __nv_bfloat16* Vl = g_VTl + (size_t)bh * DH * SKV;

    // stage Q tile: 128 rows x 64 bf16 = 1024 uint4 per buffer, 4/thread
    #pragma unroll
    for (int v = 0; v < 4; v++) {
        int lin = tid + 256 * v;
        int rr = lin >> 3, c8 = (lin & 7) * 8;
        *(uint4*)&sQh[rr * TS2 + c8] = *(const uint4*)&Qh[rr * DH + c8];
        *(uint4*)&sQl[rr * TS2 + c8] = *(const uint4*)&Ql[rr * DH + c8];
    }

    float m0 = -INFINITY, m1 = -INFINITY, l0 = 0.f, l1 = 0.f;
    float o[8][4];
    #pragma unroll
    for (int j = 0; j < 8; j++)
        #pragma unroll
        for (int e = 0; e < 4; e++) o[j][e] = 0.f;

    for (int kc = 0; kc < SKV; kc += 64) {
        __syncthreads();   // prior chunk's reads done (covers Q staging on iter 0)
        // stage K chunk: 64 rows x 64 bf16 = 512 uint4/buf, 2/thread
        #pragma unroll
        for (int v = 0; v < 2; v++) {
            int lin = tid + 256 * v;
            int rr = lin >> 3, c8 = (lin & 7) * 8;
            *(uint4*)&sKh[rr * TS2 + c8] = *(const uint4*)&Kh[(size_t)(kc + rr) * DH + c8];
            *(uint4*)&sKl[rr * TS2 + c8] = *(const uint4*)&Kl[(size_t)(kc + rr) * DH + c8];
        }
        // stage VT chunk: rows = d (0..63), cols = keys kc..kc+63
        #pragma unroll
        for (int v = 0; v < 2; v++) {
            int lin = tid + 256 * v;
            int rr = lin >> 3, c8 = (lin & 7) * 8;
            *(uint4*)&sVh[rr * TS2 + c8] = *(const uint4*)&Vh[(size_t)rr * SKV + kc + c8];
            *(uint4*)&sVl[rr * TS2 + c8] = *(const uint4*)&Vl[(size_t)rr * SKV + kc + c8];
        }
        if (tid < 64) pen[tid] = (mask[b * SKV + kc + tid] != 0u) ? 0.f : -1000000000.0f;
        __syncthreads();

        // ---- S = Q K^T over this chunk: 8 n-frags of 8 keys
        float sacc[8][4];
        #pragma unroll
        for (int j = 0; j < 8; j++)
            #pragma unroll
            for (int e = 0; e < 4; e++) sacc[j][e] = 0.f;

        #pragma unroll
        for (int t = 0; t < 4; t++) {       // d contraction, k16 steps
            int c0 = t * 16 + qc * 2;
            uint32_t ah[4], al[4];
            ah[0] = *(uint32_t*)&sQh[row0 * TS2 + c0];
            ah[1] = *(uint32_t*)&sQh[(row0 + 8) * TS2 + c0];
            ah[2] = *(uint32_t*)&sQh[row0 * TS2 + c0 + 8];
            ah[3] = *(uint32_t*)&sQh[(row0 + 8) * TS2 + c0 + 8];
            al[0] = *(uint32_t*)&sQl[row0 * TS2 + c0];
            al[1] = *(uint32_t*)&sQl[(row0 + 8) * TS2 + c0];
            al[2] = *(uint32_t*)&sQl[row0 * TS2 + c0 + 8];
            al[3] = *(uint32_t*)&sQl[(row0 + 8) * TS2 + c0 + 8];
            #pragma unroll
            for (int j = 0; j < 8; j++) {
                int kr = j * 8 + r;
                uint32_t bh2[2], bl2[2];
                bh2[0] = *(uint32_t*)&sKh[kr * TS2 + c0];
                bh2[1] = *(uint32_t*)&sKh[kr * TS2 + c0 + 8];
                bl2[0] = *(uint32_t*)&sKl[kr * TS2 + c0];
                bl2[1] = *(uint32_t*)&sKl[kr * TS2 + c0 + 8];
                MMA_BF16(sacc[j], ah, bh2);
                MMA_BF16(sacc[j], ah, bl2);
                MMA_BF16(sacc[j], al, bh2);
            }
        }

        // ---- mask + online softmax (rows row0 on [0],[1]; row0+8 on [2],[3])
        #pragma unroll
        for (int j = 0; j < 8; j++) {
            float p0 = pen[j * 8 + qc * 2];
            float p1 = pen[j * 8 + qc * 2 + 1];
            sacc[j][0] += p0; sacc[j][1] += p1;
            sacc[j][2] += p0; sacc[j][3] += p1;
        }
        float mx0 = -INFINITY, mx1 = -INFINITY;
        #pragma unroll
        for (int j = 0; j < 8; j++) {
            mx0 = fmaxf(mx0, fmaxf(sacc[j][0], sacc[j][1]));
            mx1 = fmaxf(mx1, fmaxf(sacc[j][2], sacc[j][3]));
        }
        mx0 = fmaxf(mx0, __shfl_xor_sync(0xffffffffu, mx0, 1));
        mx0 = fmaxf(mx0, __shfl_xor_sync(0xffffffffu, mx0, 2));
        mx1 = fmaxf(mx1, __shfl_xor_sync(0xffffffffu, mx1, 1));
        mx1 = fmaxf(mx1, __shfl_xor_sync(0xffffffffu, mx1, 2));
        float nm0 = fmaxf(m0, mx0), nm1 = fmaxf(m1, mx1);
        float al0 = __expf(m0 - nm0), al1 = __expf(m1 - nm1);
        float s0 = 0.f, s1 = 0.f;
        #pragma unroll
        for (int j = 0; j < 8; j++) {
            sacc[j][0] = __expf(sacc[j][0] - nm0);
            sacc[j][1] = __expf(sacc[j][1] - nm0);
            sacc[j][2] = __expf(sacc[j][2] - nm1);
            sacc[j][3] = __expf(sacc[j][3] - nm1);
            s0 += sacc[j][0] + sacc[j][1];
            s1 += sacc[j][2] + sacc[j][3];
        }
        s0 += __shfl_xor_sync(0xffffffffu, s0, 1);
        s0 += __shfl_xor_sync(0xffffffffu, s0, 2);
        s1 += __shfl_xor_sync(0xffffffffu, s1, 1);
        s1 += __shfl_xor_sync(0xffffffffu, s1, 2);
        l0 = l0 * al0 + s0;  m0 = nm0;
        l1 = l1 * al1 + s1;  m1 = nm1;
        #pragma unroll
        for (int j = 0; j < 8; j++) {
            o[j][0] *= al0; o[j][1] *= al0;
            o[j][2] *= al1; o[j][3] *= al1;
        }

        // ---- O += P V : contraction over 64 keys, output d=64 (8 n-frags)
        #pragma unroll
        for (int t = 0; t < 4; t++) {       // key k16 steps (S tiles 2t, 2t+1)
            uint32_t ph[4], pl[4];
            #pragma unroll
            for (int half = 0; half < 2; half++) {
                int jt = 2 * t + half;
                __nv_bfloat16 h0 = __float2bfloat16(sacc[jt][0]);
                __nv_bfloat16 h1 = __float2bfloat16(sacc[jt][1]);
                __nv_bfloat16 h2 = __float2bfloat16(sacc[jt][2]);
                __nv_bfloat16 h3 = __float2bfloat16(sacc[jt][3]);
                ph[half * 2 + 0] = (uint32_t)__bfloat16_as_ushort(h0) |
                                   ((uint32_t)__bfloat16_as_ushort(h1) << 16);
                ph[half * 2 + 1] = (uint32_t)__bfloat16_as_ushort(h2) |
                                   ((uint32_t)__bfloat16_as_ushort(h3) << 16);
                __nv_bfloat16 g0 = __float2bfloat16(sacc[jt][0] - __bfloat162float(h0));
                __nv_bfloat16 g1 = __float2bfloat16(sacc[jt][1] - __bfloat162float(h1));
                __nv_bfloat16 g2 = __float2bfloat16(sacc[jt][2] - __bfloat162float(h2));
                __nv_bfloat16 g3 = __float2bfloat16(sacc[jt][3] - __bfloat162float(h3));
                pl[half * 2 + 0] = (uint32_t)__bfloat16_as_ushort(g0) |
                                   ((uint32_t)__bfloat16_as_ushort(g1) << 16);
                pl[half * 2 + 1] = (uint32_t)__bfloat16_as_ushort(g2) |
                                   ((uint32_t)__bfloat16_as_ushort(g3) << 16);
            }
            // NOTE: A-frag order is {a0,a1,a2,a3} = {(r,c),(r+8,c),(r,c+8),(r+8,c+8)}
            // ph[0]=(r,c pair of tile 2t) a0; ph[1]=(r+8) a1; ph[2],ph[3] = tile 2t+1 -> a2,a3. OK.
            int c0 = t * 16 + qc * 2;
            #pragma unroll
            for (int n = 0; n < 8; n++) {
                int dr = n * 8 + r;
                uint32_t bh2[2], bl2[2];
                bh2[0] = *(uint32_t*)&sVh[dr * TS2 + c0];
                bh2[1] = *(uint32_t*)&sVh[dr * TS2 + c0 + 8];
                bl2[0] = *(uint32_t*)&sVl[dr * TS2 + c0];
                bl2[1] = *(uint32_t*)&sVl[dr * TS2 + c0 + 8];
                MMA_BF16(o[n], ph, bh2);
                MMA_BF16(o[n], ph, bl2);
                MMA_BF16(o[n], pl, bh2);
            }
        }
    }

    // final: O / l -> g_ctx[b, q0+row, h*64 + d]
    float inv0 = 1.0f / l0, inv1 = 1.0f / l1;
    #pragma unroll
    for (int n = 0; n < 8; n++) {
        int d = n * 8 + qc * 2;
        size_t a0 = ((size_t)b * SQ + q0 + row0) * DM + h * 64 + d;
        size_t a1 = ((size_t)b * SQ + q0 + row0 + 8) * DM + h * 64 + d;
        float2 v0 = make_float2(o[n][0] * inv0, o[n][1] * inv0);
        float2 v1 = make_float2(o[n][2] * inv1, o[n][3] * inv1);
        *(float2*)&g_ctx[a0] = v0;
        *(float2*)&g_ctx[a1] = v1;
    }
}

// ---------------------------------------------------------------------------
// Residual + LayerNorm, one block per row.
// ---------------------------------------------------------------------------
__global__ __launch_bounds__(256)
void ln_k(const float* __restrict__ dq, const float* __restrict__ gamma,
          const float* __restrict__ beta, float* __restrict__ out) {
    int row = blockIdx.x;
    int tid = threadIdx.x;
    __shared__ float red[256];
    __shared__ float mu_s, var_s;

    float x[4];
    float s = 0.f;
    #pragma unroll
    for (int u = 0; u < 4; u++) {
        int idx = u * 256 + tid;
        x[u] = dq[(size_t)row * DM + idx] + g_proj[(size_t)row * DM + idx];
        s += x[u];
    }
    red[tid] = s;
    __syncthreads();
    for (int st = 128; st > 0; st >>= 1) {
        if (tid < st) red[tid] += red[tid + st];
        __syncthreads();
    }
    if (tid == 0) mu_s = red[0] * (1.0f / DM);
    __syncthreads();
    float mu = mu_s;

    s = 0.f;
    #pragma unroll
    for (int u = 0; u < 4; u++) {
        float d2 = x[u] - mu;
        s += d2 * d2;
    }
    red[tid] = s;
    __syncthreads();
    for (int st = 128; st > 0; st >>= 1) {
        if (tid < st) red[tid] += red[tid + st];
        __syncthreads();
    }
    if (tid == 0) var_s = red[0] * (1.0f / DM);
    __syncthreads();
    float rstd = rsqrtf(var_s + 0.001f);

    #pragma unroll
    for (int u = 0; u < 4; u++) {
        int idx = u * 256 + tid;
        out[(size_t)row * DM + idx] = (x[u] - mu) * rstd * gamma[idx] + beta[idx];
    }
}

// ---------------------------------------------------------------------------
extern "C" void kernel_launch(void* const* d_in, const int* in_sizes, int n_in,
                              void* d_out, int out_size) {
    const float* dq    = (const float*)d_in[0];
    const float* ekv   = (const float*)d_in[1];
    const unsigned int* mask = (const unsigned int*)d_in[2];
    const float* Wq    = (const float*)d_in[3];
    const float* Wk    = (const float*)d_in[4];
    const float* Wv    = (const float*)d_in[5];
    const float* Wo    = (const float*)d_in[6];
    const float* gamma = (const float*)d_in[7];
    const float* beta  = (const float*)d_in[8];
    float* out = (float*)d_out;

    static bool attr_set = false;
    if (!attr_set) {
        cudaFuncSetAttribute(flash_k, cudaFuncAttributeMaxDynamicSharedMemorySize, FSMEM);
        attr_set = true;
    }

    rope_table_k<<<(SKV * 32 + 255) / 256, 256>>>();
    tsplit_k<0><<<dim3(32, 32), dim3(32, 8)>>>(Wq);
    tsplit_k<1><<<dim3(32, 32), dim3(32, 8)>>>(Wk);
    tsplit_k<2><<<dim3(32, 32), dim3(32, 8)>>>(Wv);
    tsplit_k<3><<<dim3(32, 32), dim3(32, 8)>>>(Wo);

    // Projections + RoPE; outputs pre-split bf16 (V transposed)
    mgemm_k<1, 0><<<dim3(8, 32), 256>>>(dq,  SQ);
    mgemm_k<2, 1><<<dim3(8, 64), 256>>>(ekv, SKV);
    mgemm_k<0, 2><<<dim3(8, 64), 256>>>(ekv, SKV);

    // Tensor-core flash attention
    flash_k<<<dim3(SQ / 128, Bb * NH), 256, FSMEM>>>(mask);

    // Output projection (A = g_ctx inside kernel)
    mgemm_k<3, 3><<<dim3(8, 32), 256>>>(nullptr, SQ);

    // Residual + LayerNorm
    ln_k<<<Bb * SQ, 256>>>(dq, gamma, beta, out);
}

// round 11
// speedup vs baseline: 2.4612x; 1.1982x over previous
#include <cuda_runtime.h>
#include <cuda_bf16.h>
#include <math.h>
#include <stdint.h>

#define Bb 4
#define SQ 1024
#define SKV 2048
#define DM 1024
#define NH 16
#define DH 64

#define NA0 (Bb*SQ*DM)    // dq / ctx element count
#define NA1 (Bb*SKV*DM)   // ekv element count

// ---------------------------------------------------------------------------
// Scratch (device globals; referenced ONLY inside device code — never passed
// as kernel args from host).
// ---------------------------------------------------------------------------
__device__ __align__(16) float g_ctx[Bb*SQ*DM];      // [B,Sq,H*Dh]
__device__ __align__(16) float g_proj[Bb*SQ*DM];     // [B,Sq,DM]
__device__ __align__(16) float g_rc[SKV*32];         // rope cos [s][pair]
__device__ __align__(16) float g_rs[SKV*32];         // rope sin [s][pair]
// transposed [N,K] bf16 weight splits: 0=Wq 1=Wk 2=Wv 3=Wo
__device__ __align__(16) __nv_bfloat16 g_Wth[4][DM*DM];
__device__ __align__(16) __nv_bfloat16 g_Wtl[4][DM*DM];
// pre-split activations (GEMM A operands): 0=dq 1=ekv 2=ctx
__device__ __align__(16) __nv_bfloat16 g_Ah0[NA0], g_Al0[NA0];
__device__ __align__(16) __nv_bfloat16 g_Ah1[NA1], g_Al1[NA1];
__device__ __align__(16) __nv_bfloat16 g_Ah2[NA0], g_Al2[NA0];
// attention operands, bf16 hi/lo splits
__device__ __align__(16) __nv_bfloat16 g_Qbh[Bb*NH*SQ*DH],  g_Qbl[Bb*NH*SQ*DH];   // [b,h,s,d]
__device__ __align__(16) __nv_bfloat16 g_Kbh[Bb*NH*SKV*DH], g_Kbl[Bb*NH*SKV*DH];  // [b,h,s,d]
__device__ __align__(16) __nv_bfloat16 g_VTh[Bb*NH*DH*SKV], g_VTl[Bb*NH*DH*SKV];  // [b,h,d,s]

// ---------------------------------------------------------------------------
// mma.sync bf16: D(16x8) += A(16x16,row) * B(16x8,col), fp32 accum
// ---------------------------------------------------------------------------
#define MMA_BF16(d, a, b) \
    asm volatile("mma.sync.aligned.m16n8k16.row.col.f32.bf16.bf16.f32 " \
        "{%0,%1,%2,%3}, {%4,%5,%6,%7}, {%8,%9}, {%0,%1,%2,%3};" \
        : "+f"((d)[0]), "+f"((d)[1]), "+f"((d)[2]), "+f"((d)[3]) \
        : "r"((a)[0]), "r"((a)[1]), "r"((a)[2]), "r"((a)[3]), \
          "r"((b)[0]), "r"((b)[1]))

__device__ __forceinline__ void split2(float a, float b, uint32_t& hp, uint32_t& lp) {
    __nv_bfloat16 ha = __float2bfloat16(a), hb = __float2bfloat16(b);
    float la = a - __bfloat162float(ha);
    float lb = b - __bfloat162float(hb);
    __nv_bfloat16 hla = __float2bfloat16(la), hlb = __float2bfloat16(lb);
    hp = (uint32_t)__bfloat16_as_ushort(ha) | ((uint32_t)__bfloat16_as_ushort(hb) << 16);
    lp = (uint32_t)__bfloat16_as_ushort(hla) | ((uint32_t)__bfloat16_as_ushort(hlb) << 16);
}

__device__ __forceinline__ void cpa16(void* dst, const void* src) {
    uint32_t sa = (uint32_t)__cvta_generic_to_shared(dst);
    asm volatile("cp.async.cg.shared.global [%0], [%1], 16;" :: "r"(sa), "l"(src));
}
#define CPA_COMMIT() asm volatile("cp.async.commit_group;" ::: "memory")
#define CPA_WAIT1()  asm volatile("cp.async.wait_group 1;" ::: "memory")
#define CPA_WAIT0()  asm volatile("cp.async.wait_group 0;" ::: "memory")

// ---------------------------------------------------------------------------
// Prep
// ---------------------------------------------------------------------------
__global__ void rope_table_k() {
    int idx = blockIdx.x * blockDim.x + threadIdx.x;
    if (idx >= SKV * 32) return;
    int s = idx >> 5, p = idx & 31;
    double inv = pow(10000.0, -(double)(2 * p) / 64.0);
    double ang = (double)s * inv;
    g_rc[idx] = (float)cos(ang);
    g_rs[idx] = (float)sin(ang);
}

template<int WIDX>
__global__ void tsplit_k(const float* __restrict__ W) {
    __shared__ float t[32][33];
    int n0 = blockIdx.x * 32, k0 = blockIdx.y * 32;
    int tx = threadIdx.x, ty = threadIdx.y;    // 32 x 8
    #pragma unroll
    for (int r = 0; r < 32; r += 8)
        t[ty + r][tx] = W[(k0 + ty + r) * DM + n0 + tx];
    __syncthreads();
    __nv_bfloat16* Th = g_Wth[WIDX];
    __nv_bfloat16* Tl = g_Wtl[WIDX];
    #pragma unroll
    for (int r = 0; r < 32; r += 8) {
        float v = t[tx][ty + r];
        __nv_bfloat16 hh = __float2bfloat16(v);
        int o = (n0 + ty + r) * DM + k0 + tx;
        Th[o] = hh;
        Tl[o] = __float2bfloat16(v - __bfloat162float(hh));
    }
}

// activation split: DST 0=dq 1=ekv (arg pointer), 2=g_ctx (internal)
template<int DST>
__global__ void asplit_k(const float* __restrict__ X) {
    int i = (blockIdx.x * blockDim.x + threadIdx.x) * 4;
    const float* src = (DST == 2) ? g_ctx : X;
    __nv_bfloat16* Ah = (DST == 0) ? g_Ah0 : (DST == 1) ? g_Ah1 : g_Ah2;
    __nv_bfloat16* Al = (DST == 0) ? g_Al0 : (DST == 1) ? g_Al1 : g_Al2;
    float4 v = *(const float4*)(src + i);
    uint32_t h0, l0, h1, l1;
    split2(v.x, v.y, h0, l0);
    split2(v.z, v.w, h1, l1);
    *(uint2*)&Ah[i] = make_uint2(h0, h1);
    *(uint2*)&Al[i] = make_uint2(l0, l1);
}

// ---------------------------------------------------------------------------
// mma.sync GEMM, cp.async double-buffered. All operands internal bf16 splits.
// MODE 0: V -> g_VT h/l (transposed)  MODE 1: Q (rope+0.125) -> g_Qb h/l
// MODE 2: K (rope) -> g_Kb h/l        MODE 3: -> g_proj (fp32)
// Tile 128x128, KC=32, 8 warps, warp tile 64x32; 2-stage pipeline.
// ---------------------------------------------------------------------------
#define KC    32
#define TSTR  40
#define GTILE (128*TSTR)
#define GSMEM (2*4*GTILE*2)   // 2 stages x 4 tiles x bf16 = 81920 B

template<int MODE, int WIDX, int AIDX>
__global__ __launch_bounds__(256)
void mgemm_k(int S) {
    extern __shared__ __align__(16) __nv_bfloat16 smg[];

    const __nv_bfloat16* Ah = (AIDX == 0) ? g_Ah0 : (AIDX == 1) ? g_Ah1 : g_Ah2;
    const __nv_bfloat16* Al = (AIDX == 0) ? g_Al0 : (AIDX == 1) ? g_Al1 : g_Al2;
    const __nv_bfloat16* Wh = g_Wth[WIDX];
    const __nv_bfloat16* Wl = g_Wtl[WIDX];

    int tid = threadIdx.x, wid = tid >> 5, lane = tid & 31;
    int wr = wid >> 2, wc = wid & 3;
    int qr = lane >> 2, qc = lane & 3;
    const int arow0 = blockIdx.y * 128, bcol0 = blockIdx.x * 128;

    float acc[4][4][4];
    #pragma unroll
    for (int mi = 0; mi < 4; mi++)
        #pragma unroll
        for (int ni = 0; ni < 4; ni++)
            #pragma unroll
            for (int e = 0; e < 4; e++) acc[mi][ni][e] = 0.f;

    // stage chunk (kt) into buffer s
    auto stage = [&](int kt, int s) {
        __nv_bfloat16* dAh = smg + (size_t)s * 4 * GTILE;
        __nv_bfloat16* dAl = dAh + GTILE;
        __nv_bfloat16* dBh = dAl + GTILE;
        __nv_bfloat16* dBl = dBh + GTILE;
        #pragma unroll
        for (int v = 0; v < 2; v++) {
            int lin = tid + 256 * v;
            int r = lin >> 2, c = (lin & 3) * 8;
            size_t ga = (size_t)(arow0 + r) * DM + kt + c;
            size_t gb = (size_t)(bcol0 + r) * DM + kt + c;
            cpa16(&dAh[r * TSTR + c], Ah + ga);
            cpa16(&dAl[r * TSTR + c], Al + ga);
            cpa16(&dBh[r * TSTR + c], Wh + gb);
            cpa16(&dBl[r * TSTR + c], Wl + gb);
        }
    };

    stage(0, 0);
    CPA_COMMIT();

    const int NC = DM / KC;   // 32
    for (int c = 0; c < NC; c++) {
        if (c + 1 < NC) {
            stage((c + 1) * KC, (c + 1) & 1);
            CPA_COMMIT();
            CPA_WAIT1();
        } else {
            CPA_WAIT0();
        }
        __syncthreads();

        const __nv_bfloat16* sAh = smg + (size_t)(c & 1) * 4 * GTILE;
        const __nv_bfloat16* sAl = sAh + GTILE;
        const __nv_bfloat16* sBh = sAl + GTILE;
        const __nv_bfloat16* sBl = sBh + GTILE;

        #pragma unroll
        for (int k16 = 0; k16 < KC; k16 += 16) {
            int c0 = k16 + qc * 2;
            uint32_t af[4][4], bf[4][2];
            #pragma unroll
            for (int mi = 0; mi < 4; mi++) {
                int r0 = wr * 64 + mi * 16 + qr;
                af[mi][0] = *(uint32_t*)&sAh[r0 * TSTR + c0];
                af[mi][1] = *(uint32_t*)&sAh[(r0 + 8) * TSTR + c0];
                af[mi][2] = *(uint32_t*)&sAh[r0 * TSTR + c0 + 8];
                af[mi][3] = *(uint32_t*)&sAh[(r0 + 8) * TSTR + c0 + 8];
            }
            #pragma unroll
            for (int ni = 0; ni < 4; ni++) {
                int r0 = wc * 32 + ni * 8 + qr;
                bf[ni][0] = *(uint32_t*)&sBh[r0 * TSTR + c0];
                bf[ni][1] = *(uint32_t*)&sBh[r0 * TSTR + c0 + 8];
            }
            #pragma unroll
            for (int mi = 0; mi < 4; mi++)
                #pragma unroll
                for (int ni = 0; ni < 4; ni++)
                    MMA_BF16(acc[mi][ni], af[mi], bf[ni]);

            #pragma unroll
            for (int ni = 0; ni < 4; ni++) {
                int r0 = wc * 32 + ni * 8 + qr;
                bf[ni][0] = *(uint32_t*)&sBl[r0 * TSTR + c0];
                bf[ni][1] = *(uint32_t*)&sBl[r0 * TSTR + c0 + 8];
            }
            #pragma unroll
            for (int mi = 0; mi < 4; mi++)
                #pragma unroll
                for (int ni = 0; ni < 4; ni++)
                    MMA_BF16(acc[mi][ni], af[mi], bf[ni]);

            #pragma unroll
            for (int mi = 0; mi < 4; mi++) {
                int r0 = wr * 64 + mi * 16 + qr;
                af[mi][0] = *(uint32_t*)&sAl[r0 * TSTR + c0];
                af[mi][1] = *(uint32_t*)&sAl[(r0 + 8) * TSTR + c0];
                af[mi][2] = *(uint32_t*)&sAl[r0 * TSTR + c0 + 8];
                af[mi][3] = *(uint32_t*)&sAl[(r0 + 8) * TSTR + c0 + 8];
            }
            #pragma unroll
            for (int ni = 0; ni < 4; ni++) {
                int r0 = wc * 32 + ni * 8 + qr;
                bf[ni][0] = *(uint32_t*)&sBh[r0 * TSTR + c0];
                bf[ni][1] = *(uint32_t*)&sBh[r0 * TSTR + c0 + 8];
            }
            #pragma unroll
            for (int mi = 0; mi < 4; mi++)
                #pragma unroll
                for (int ni = 0; ni < 4; ni++)
                    MMA_BF16(acc[mi][ni], af[mi], bf[ni]);
        }
        __syncthreads();   // reads done before buffer is restaged at c+2
    }

    // Epilogue (R10-validated)
    #pragma unroll
    for (int mi = 0; mi < 4; mi++) {
        #pragma unroll
        for (int half = 0; half < 2; half++) {
            int m = arow0 + wr * 64 + mi * 16 + qr + half * 8;
            int bb = m / S, s = m - bb * S;
            #pragma unroll
            for (int ni = 0; ni < 4; ni++) {
                int n = bcol0 + wc * 32 + ni * 8 + qc * 2;   // even
                float o1 = acc[mi][ni][half * 2 + 0];
                float o2 = acc[mi][ni][half * 2 + 1];
                if (MODE == 3) {
                    g_proj[(size_t)m * DM + n]     = o1;
                    g_proj[(size_t)m * DM + n + 1] = o2;
                } else {
                    int hh = n >> 6, d0 = n & 63;
                    if (MODE == 0) {
                        size_t vb = ((size_t)(bb * NH + hh) * DH) * SKV + s;
                        __nv_bfloat16 h1 = __float2bfloat16(o1);
                        __nv_bfloat16 h2 = __float2bfloat16(o2);
                        g_VTh[vb + (size_t)d0 * SKV]       = h1;
                        g_VTh[vb + (size_t)(d0 + 1) * SKV] = h2;
                        g_VTl[vb + (size_t)d0 * SKV]       = __float2bfloat16(o1 - __bfloat162float(h1));
                        g_VTl[vb + (size_t)(d0 + 1) * SKV] = __float2bfloat16(o2 - __bfloat162float(h2));
                    } else {
                        int ti = s * 32 + (d0 >> 1);
                        float co = g_rc[ti], sn = g_rs[ti];
                        float r1 = o1 * co - o2 * sn;
                        float r2 = o2 * co + o1 * sn;
                        if (MODE == 1) { r1 *= 0.125f; r2 *= 0.125f; }
                        size_t base = ((size_t)(bb * NH + hh) * S + s) * DH + d0;
                        uint32_t hp, lp;
                        split2(r1, r2, hp, lp);
                        if (MODE == 1) {
                            *(uint32_t*)&g_Qbh[base] = hp;
                            *(uint32_t*)&g_Qbl[base] = lp;
                        } else {
                            *(uint32_t*)&g_Kbh[base] = hp;
                            *(uint32_t*)&g_Kbl[base] = lp;
                        }
                    }
                }
            }
        }
    }
}

// ---------------------------------------------------------------------------
// Tensor-core flash attention (R10-validated). Grid (SQ/128, B*NH), 256 thr.
// ---------------------------------------------------------------------------
#define TS2 72
#define OQH 0
#define OQL (OQH + 128*TS2*2)
#define OKH (OQL + 128*TS2*2)
#define OKL (OKH + 64*TS2*2)
#define OVH (OKL + 64*TS2*2)
#define OVL (OVH + 64*TS2*2)
#define OPEN (OVL + 64*TS2*2)
#define FSMEM (OPEN + 64*4)

__global__ __launch_bounds__(256)
void flash_k(const unsigned int* __restrict__ mask) {
    extern __shared__ __align__(16) char sm[];
    __nv_bfloat16* sQh = (__nv_bfloat16*)(sm + OQH);
    __nv_bfloat16* sQl = (__nv_bfloat16*)(sm + OQL);
    __nv_bfloat16* sKh = (__nv_bfloat16*)(sm + OKH);
    __nv_bfloat16* sKl = (__nv_bfloat16*)(sm + OKL);
    __nv_bfloat16* sVh = (__nv_bfloat16*)(sm + OVH);
    __nv_bfloat16* sVl = (__nv_bfloat16*)(sm + OVL);
    float* pen = (float*)(sm + OPEN);

    int tid = threadIdx.x, w = tid >> 5, lane = tid & 31;
    int r = lane >> 2, qc = lane & 3;
    int q0 = blockIdx.x * 128;
    int bh = blockIdx.y;
    int b = bh >> 4, h = bh & 15;
    int row0 = w * 16 + r;

    const __nv_bfloat16* Qh = g_Qbh + (size_t)bh * SQ * DH + (size_t)q0 * DH;
    const __nv_bfloat16* Ql = g_Qbl + (size_t)bh * SQ * DH + (size_t)q0 * DH;
    const __nv_bfloat16* Kh = g_Kbh + (size_t)bh * SKV * DH;
    const __nv_bfloat16* Kl = g_Kbl + (size_t)bh * SKV * DH;
    const __nv_bfloat16* Vh = g_VTh + (size_t)bh * DH * SKV;
    const __nv_bfloat16* Vl = g_VTl + (size_t)bh * DH * SKV;

    #pragma unroll
    for (int v = 0; v < 4; v++) {
        int lin = tid + 256 * v;
        int rr = lin >> 3, c8 = (lin & 7) * 8;
        *(uint4*)&sQh[rr * TS2 + c8] = *(const uint4*)&Qh[rr * DH + c8];
        *(uint4*)&sQl[rr * TS2 + c8] = *(const uint4*)&Ql[rr * DH + c8];
    }

    float m0 = -INFINITY, m1 = -INFINITY, l0 = 0.f, l1 = 0.f;
    float o[8][4];
    #pragma unroll
    for (int j = 0; j < 8; j++)
        #pragma unroll
        for (int e = 0; e < 4; e++) o[j][e] = 0.f;

    for (int kc = 0; kc < SKV; kc += 64) {
        __syncthreads();
        #pragma unroll
        for (int v = 0; v < 2; v++) {
            int lin = tid + 256 * v;
            int rr = lin >> 3, c8 = (lin & 7) * 8;
            *(uint4*)&sKh[rr * TS2 + c8] = *(const uint4*)&Kh[(size_t)(kc + rr) * DH + c8];
            *(uint4*)&sKl[rr * TS2 + c8] = *(const uint4*)&Kl[(size_t)(kc + rr) * DH + c8];
        }
        #pragma unroll
        for (int v = 0; v < 2; v++) {
            int lin = tid + 256 * v;
            int rr = lin >> 3, c8 = (lin & 7) * 8;
            *(uint4*)&sVh[rr * TS2 + c8] = *(const uint4*)&Vh[(size_t)rr * SKV + kc + c8];
            *(uint4*)&sVl[rr * TS2 + c8] = *(const uint4*)&Vl[(size_t)rr * SKV + kc + c8];
        }
        if (tid < 64) pen[tid] = (mask[b * SKV + kc + tid] != 0u) ? 0.f : -1000000000.0f;
        __syncthreads();

        float sacc[8][4];
        #pragma unroll
        for (int j = 0; j < 8; j++)
            #pragma unroll
            for (int e = 0; e < 4; e++) sacc[j][e] = 0.f;

        #pragma unroll
        for (int t = 0; t < 4; t++) {
            int c0 = t * 16 + qc * 2;
            uint32_t ah[4], al[4];
            ah[0] = *(uint32_t*)&sQh[row0 * TS2 + c0];
            ah[1] = *(uint32_t*)&sQh[(row0 + 8) * TS2 + c0];
            ah[2] = *(uint32_t*)&sQh[row0 * TS2 + c0 + 8];
            ah[3] = *(uint32_t*)&sQh[(row0 + 8) * TS2 + c0 + 8];
            al[0] = *(uint32_t*)&sQl[row0 * TS2 + c0];
            al[1] = *(uint32_t*)&sQl[(row0 + 8) * TS2 + c0];
            al[2] = *(uint32_t*)&sQl[row0 * TS2 + c0 + 8];
            al[3] = *(uint32_t*)&sQl[(row0 + 8) * TS2 + c0 + 8];
            #pragma unroll
            for (int j = 0; j < 8; j++) {
                int kr = j * 8 + r;
                uint32_t bh2[2], bl2[2];
                bh2[0] = *(uint32_t*)&sKh[kr * TS2 + c0];
                bh2[1] = *(uint32_t*)&sKh[kr * TS2 + c0 + 8];
                bl2[0] = *(uint32_t*)&sKl[kr * TS2 + c0];
                bl2[1] = *(uint32_t*)&sKl[kr * TS2 + c0 + 8];
                MMA_BF16(sacc[j], ah, bh2);
                MMA_BF16(sacc[j], ah, bl2);
                MMA_BF16(sacc[j], al, bh2);
            }
        }

        #pragma unroll
        for (int j = 0; j < 8; j++) {
            float p0 = pen[j * 8 + qc * 2];
            float p1 = pen[j * 8 + qc * 2 + 1];
            sacc[j][0] += p0; sacc[j][1] += p1;
            sacc[j][2] += p0; sacc[j][3] += p1;
        }
        float mx0 = -INFINITY, mx1 = -INFINITY;
        #pragma unroll
        for (int j = 0; j < 8; j++) {
            mx0 = fmaxf(mx0, fmaxf(sacc[j][0], sacc[j][1]));
            mx1 = fmaxf(mx1, fmaxf(sacc[j][2], sacc[j][3]));
        }
        mx0 = fmaxf(mx0, __shfl_xor_sync(0xffffffffu, mx0, 1));
        mx0 = fmaxf(mx0, __shfl_xor_sync(0xffffffffu, mx0, 2));
        mx1 = fmaxf(mx1, __shfl_xor_sync(0xffffffffu, mx1, 1));
        mx1 = fmaxf(mx1, __shfl_xor_sync(0xffffffffu, mx1, 2));
        float nm0 = fmaxf(m0, mx0), nm1 = fmaxf(m1, mx1);
        float al0 = __expf(m0 - nm0), al1 = __expf(m1 - nm1);
        float s0 = 0.f, s1 = 0.f;
        #pragma unroll
        for (int j = 0; j < 8; j++) {
            sacc[j][0] = __expf(sacc[j][0] - nm0);
            sacc[j][1] = __expf(sacc[j][1] - nm0);
            sacc[j][2] = __expf(sacc[j][2] - nm1);
            sacc[j][3] = __expf(sacc[j][3] - nm1);
            s0 += sacc[j][0] + sacc[j][1];
            s1 += sacc[j][2] + sacc[j][3];
        }
        s0 += __shfl_xor_sync(0xffffffffu, s0, 1);
        s0 += __shfl_xor_sync(0xffffffffu, s0, 2);
        s1 += __shfl_xor_sync(0xffffffffu, s1, 1);
        s1 += __shfl_xor_sync(0xffffffffu, s1, 2);
        l0 = l0 * al0 + s0;  m0 = nm0;
        l1 = l1 * al1 + s1;  m1 = nm1;
        #pragma unroll
        for (int j = 0; j < 8; j++) {
            o[j][0] *= al0; o[j][1] *= al0;
            o[j][2] *= al1; o[j][3] *= al1;
        }

        #pragma unroll
        for (int t = 0; t < 4; t++) {
            uint32_t ph[4], pl[4];
            #pragma unroll
            for (int half = 0; half < 2; half++) {
                int jt = 2 * t + half;
                __nv_bfloat16 h0 = __float2bfloat16(sacc[jt][0]);
                __nv_bfloat16 h1 = __float2bfloat16(sacc[jt][1]);
                __nv_bfloat16 h2 = __float2bfloat16(sacc[jt][2]);
                __nv_bfloat16 h3 = __float2bfloat16(sacc[jt][3]);
                ph[half * 2 + 0] = (uint32_t)__bfloat16_as_ushort(h0) |
                                   ((uint32_t)__bfloat16_as_ushort(h1) << 16);
                ph[half * 2 + 1] = (uint32_t)__bfloat16_as_ushort(h2) |
                                   ((uint32_t)__bfloat16_as_ushort(h3) << 16);
                __nv_bfloat16 g0 = __float2bfloat16(sacc[jt][0] - __bfloat162float(h0));
                __nv_bfloat16 g1 = __float2bfloat16(sacc[jt][1] - __bfloat162float(h1));
                __nv_bfloat16 g2 = __float2bfloat16(sacc[jt][2] - __bfloat162float(h2));
                __nv_bfloat16 g3 = __float2bfloat16(sacc[jt][3] - __bfloat162float(h3));
                pl[half * 2 + 0] = (uint32_t)__bfloat16_as_ushort(g0) |
                                   ((uint32_t)__bfloat16_as_ushort(g1) << 16);
                pl[half * 2 + 1] = (uint32_t)__bfloat16_as_ushort(g2) |
                                   ((uint32_t)__bfloat16_as_ushort(g3) << 16);
            }
            int c0 = t * 16 + qc * 2;
            #pragma unroll
            for (int n = 0; n < 8; n++) {
                int dr = n * 8 + r;
                uint32_t bh2[2], bl2[2];
                bh2[0] = *(uint32_t*)&sVh[dr * TS2 + c0];
                bh2[1] = *(uint32_t*)&sVh[dr * TS2 + c0 + 8];
                bl2[0] = *(uint32_t*)&sVl[dr * TS2 + c0];
                bl2[1] = *(uint32_t*)&sVl[dr * TS2 + c0 + 8];
                MMA_BF16(o[n], ph, bh2);
                MMA_BF16(o[n], ph, bl2);
                MMA_BF16(o[n], pl, bh2);
            }
        }
    }

    float inv0 = 1.0f / l0, inv1 = 1.0f / l1;
    #pragma unroll
    for (int n = 0; n < 8; n++) {
        int d = n * 8 + qc * 2;
        size_t a0 = ((size_t)b * SQ + q0 + row0) * DM + h * 64 + d;
        size_t a1 = ((size_t)b * SQ + q0 + row0 + 8) * DM + h * 64 + d;
        *(float2*)&g_ctx[a0] = make_float2(o[n][0] * inv0, o[n][1] * inv0);
        *(float2*)&g_ctx[a1] = make_float2(o[n][2] * inv1, o[n][3] * inv1);
    }
}

// ---------------------------------------------------------------------------
// Residual + LayerNorm, one block per row.
// ---------------------------------------------------------------------------
__global__ __launch_bounds__(256)
void ln_k(const float* __restrict__ dq, const float* __restrict__ gamma,
          const float* __restrict__ beta, float* __restrict__ out) {
    int row = blockIdx.x;
    int tid = threadIdx.x;
    __shared__ float red[256];
    __shared__ float mu_s, var_s;

    float x[4];
    float s = 0.f;
    #pragma unroll
    for (int u = 0; u < 4; u++) {
        int idx = u * 256 + tid;
        x[u] = dq[(size_t)row * DM + idx] + g_proj[(size_t)row * DM + idx];
        s += x[u];
    }
    red[tid] = s;
    __syncthreads();
    for (int st = 128; st > 0; st >>= 1) {
        if (tid < st) red[tid] += red[tid + st];
        __syncthreads();
    }
    if (tid == 0) mu_s = red[0] * (1.0f / DM);
    __syncthreads();
    float mu = mu_s;

    s = 0.f;
    #pragma unroll
    for (int u = 0; u < 4; u++) {
        float d2 = x[u] - mu;
        s += d2 * d2;
    }
    red[tid] = s;
    __syncthreads();
    for (int st = 128; st > 0; st >>= 1) {
        if (tid < st) red[tid] += red[tid + st];
        __syncthreads();
    }
    if (tid == 0) var_s = red[0] * (1.0f / DM);
    __syncthreads();
    float rstd = rsqrtf(var_s + 0.001f);

    #pragma unroll
    for (int u = 0; u < 4; u++) {
        int idx = u * 256 + tid;
        out[(size_t)row * DM + idx] = (x[u] - mu) * rstd * gamma[idx] + beta[idx];
    }
}

// ---------------------------------------------------------------------------
extern "C" void kernel_launch(void* const* d_in, const int* in_sizes, int n_in,
                              void* d_out, int out_size) {
    const float* dq    = (const float*)d_in[0];
    const float* ekv   = (const float*)d_in[1];
    const unsigned int* mask = (const unsigned int*)d_in[2];
    const float* Wq    = (const float*)d_in[3];
    const float* Wk    = (const float*)d_in[4];
    const float* Wv    = (const float*)d_in[5];
    const float* Wo    = (const float*)d_in[6];
    const float* gamma = (const float*)d_in[7];
    const float* beta  = (const float*)d_in[8];
    float* out = (float*)d_out;

    static bool attr_set = false;
    if (!attr_set) {
        cudaFuncSetAttribute(flash_k, cudaFuncAttributeMaxDynamicSharedMemorySize, FSMEM);
        cudaFuncSetAttribute(mgemm_k<1, 0, 0>, cudaFuncAttributeMaxDynamicSharedMemorySize, GSMEM);
        cudaFuncSetAttribute(mgemm_k<2, 1, 1>, cudaFuncAttributeMaxDynamicSharedMemorySize, GSMEM);
        cudaFuncSetAttribute(mgemm_k<0, 2, 1>, cudaFuncAttributeMaxDynamicSharedMemorySize, GSMEM);
        cudaFuncSetAttribute(mgemm_k<3, 3, 2>, cudaFuncAttributeMaxDynamicSharedMemorySize, GSMEM);
        attr_set = true;
    }

    // Prep
    rope_table_k<<<(SKV * 32 + 255) / 256, 256>>>();
    tsplit_k<0><<<dim3(32, 32), dim3(32, 8)>>>(Wq);
    tsplit_k<1><<<dim3(32, 32), dim3(32, 8)>>>(Wk);
    tsplit_k<2><<<dim3(32, 32), dim3(32, 8)>>>(Wv);
    tsplit_k<3><<<dim3(32, 32), dim3(32, 8)>>>(Wo);
    asplit_k<0><<<NA0 / 1024, 256>>>(dq);
    asplit_k<1><<<NA1 / 1024, 256>>>(ekv);

    // Projections + RoPE (cp.async double-buffered GEMMs)
    mgemm_k<1, 0, 0><<<dim3(8, 32), 256, GSMEM>>>(SQ);
    mgemm_k<2, 1, 1><<<dim3(8, 64), 256, GSMEM>>>(SKV);
    mgemm_k<0, 2, 1><<<dim3(8, 64), 256, GSMEM>>>(SKV);

    // Tensor-core flash attention
    flash_k<<<dim3(SQ / 128, Bb * NH), 256, FSMEM>>>(mask);

    // Output projection
    asplit_k<2><<<NA0 / 1024, 256>>>(nullptr);
    mgemm_k<3, 3, 2><<<dim3(8, 32), 256, GSMEM>>>(SQ);

    // Residual + LayerNorm
    ln_k<<<Bb * SQ, 256>>>(dq, gamma, beta, out);
}

// round 12
// speedup vs baseline: 2.6860x; 1.0914x over previous
#include <cuda_runtime.h>
#include <cuda_bf16.h>
#include <math.h>
#include <stdint.h>

#define Bb 4
#define SQ 1024
#define SKV 2048
#define DM 1024
#define NH 16
#define DH 64

#define NA0 (Bb*SQ*DM)    // dq / ctx element count
#define NA1 (Bb*SKV*DM)   // ekv element count

// ---------------------------------------------------------------------------
// Scratch (device globals; referenced ONLY inside device code — never passed
// as kernel args from host).
// ---------------------------------------------------------------------------
__device__ __align__(16) float g_proj[Bb*SQ*DM];     // [B,Sq,DM]
__device__ __align__(16) float g_rc[SKV*32];         // rope cos [s][pair]
__device__ __align__(16) float g_rs[SKV*32];         // rope sin [s][pair]
// transposed [N,K] bf16 weight splits: 0=Wq 1=Wk 2=Wv 3=Wo
__device__ __align__(16) __nv_bfloat16 g_Wth[4][DM*DM];
__device__ __align__(16) __nv_bfloat16 g_Wtl[4][DM*DM];
// pre-split activations (GEMM A operands): 0=dq 1=ekv 2=ctx(from flash)
__device__ __align__(16) __nv_bfloat16 g_Ah0[NA0], g_Al0[NA0];
__device__ __align__(16) __nv_bfloat16 g_Ah1[NA1], g_Al1[NA1];
__device__ __align__(16) __nv_bfloat16 g_Ah2[NA0], g_Al2[NA0];
// attention operands, bf16 hi/lo splits
__device__ __align__(16) __nv_bfloat16 g_Qbh[Bb*NH*SQ*DH],  g_Qbl[Bb*NH*SQ*DH];   // [b,h,s,d]
__device__ __align__(16) __nv_bfloat16 g_Kbh[Bb*NH*SKV*DH], g_Kbl[Bb*NH*SKV*DH];  // [b,h,s,d]
__device__ __align__(16) __nv_bfloat16 g_VTh[Bb*NH*DH*SKV], g_VTl[Bb*NH*DH*SKV];  // [b,h,d,s]

// ---------------------------------------------------------------------------
// mma.sync bf16: D(16x8) += A(16x16,row) * B(16x8,col), fp32 accum
// ---------------------------------------------------------------------------
#define MMA_BF16(d, a, b) \
    asm volatile("mma.sync.aligned.m16n8k16.row.col.f32.bf16.bf16.f32 " \
        "{%0,%1,%2,%3}, {%4,%5,%6,%7}, {%8,%9}, {%0,%1,%2,%3};" \
        : "+f"((d)[0]), "+f"((d)[1]), "+f"((d)[2]), "+f"((d)[3]) \
        : "r"((a)[0]), "r"((a)[1]), "r"((a)[2]), "r"((a)[3]), \
          "r"((b)[0]), "r"((b)[1]))

__device__ __forceinline__ void split2(float a, float b, uint32_t& hp, uint32_t& lp) {
    __nv_bfloat16 ha = __float2bfloat16(a), hb = __float2bfloat16(b);
    float la = a - __bfloat162float(ha);
    float lb = b - __bfloat162float(hb);
    __nv_bfloat16 hla = __float2bfloat16(la), hlb = __float2bfloat16(lb);
    hp = (uint32_t)__bfloat16_as_ushort(ha) | ((uint32_t)__bfloat16_as_ushort(hb) << 16);
    lp = (uint32_t)__bfloat16_as_ushort(hla) | ((uint32_t)__bfloat16_as_ushort(hlb) << 16);
}

__device__ __forceinline__ void cpa16(void* dst, const void* src) {
    uint32_t sa = (uint32_t)__cvta_generic_to_shared(dst);
    asm volatile("cp.async.cg.shared.global [%0], [%1], 16;" :: "r"(sa), "l"(src));
}
#define CPA_COMMIT() asm volatile("cp.async.commit_group;" ::: "memory")
#define CPA_WAIT1()  asm volatile("cp.async.wait_group 1;" ::: "memory")
#define CPA_WAIT0()  asm volatile("cp.async.wait_group 0;" ::: "memory")

// ---------------------------------------------------------------------------
// Prep
// ---------------------------------------------------------------------------
__global__ void rope_table_k() {
    int idx = blockIdx.x * blockDim.x + threadIdx.x;
    if (idx >= SKV * 32) return;
    int s = idx >> 5, p = idx & 31;
    double inv = pow(10000.0, -(double)(2 * p) / 64.0);
    double ang = (double)s * inv;
    g_rc[idx] = (float)cos(ang);
    g_rs[idx] = (float)sin(ang);
}

template<int WIDX>
__global__ void tsplit_k(const float* __restrict__ W) {
    __shared__ float t[32][33];
    int n0 = blockIdx.x * 32, k0 = blockIdx.y * 32;
    int tx = threadIdx.x, ty = threadIdx.y;    // 32 x 8
    #pragma unroll
    for (int r = 0; r < 32; r += 8)
        t[ty + r][tx] = W[(k0 + ty + r) * DM + n0 + tx];
    __syncthreads();
    __nv_bfloat16* Th = g_Wth[WIDX];
    __nv_bfloat16* Tl = g_Wtl[WIDX];
    #pragma unroll
    for (int r = 0; r < 32; r += 8) {
        float v = t[tx][ty + r];
        __nv_bfloat16 hh = __float2bfloat16(v);
        int o = (n0 + ty + r) * DM + k0 + tx;
        Th[o] = hh;
        Tl[o] = __float2bfloat16(v - __bfloat162float(hh));
    }
}

// activation split: DST 0=dq 1=ekv (arg pointers)
template<int DST>
__global__ void asplit_k(const float* __restrict__ X) {
    int i = (blockIdx.x * blockDim.x + threadIdx.x) * 4;
    __nv_bfloat16* Ah = (DST == 0) ? g_Ah0 : g_Ah1;
    __nv_bfloat16* Al = (DST == 0) ? g_Al0 : g_Al1;
    float4 v = *(const float4*)(X + i);
    uint32_t h0, l0, h1, l1;
    split2(v.x, v.y, h0, l0);
    split2(v.z, v.w, h1, l1);
    *(uint2*)&Ah[i] = make_uint2(h0, h1);
    *(uint2*)&Al[i] = make_uint2(l0, l1);
}

// ---------------------------------------------------------------------------
// mma.sync GEMM, cp.async double-buffered (R11-validated).
// MODE 0: V -> g_VT h/l (transposed)  MODE 1: Q (rope+0.125) -> g_Qb h/l
// MODE 2: K (rope) -> g_Kb h/l        MODE 3: -> g_proj (fp32)
// ---------------------------------------------------------------------------
#define KC    32
#define TSTR  40
#define GTILE (128*TSTR)
#define GSMEM (2*4*GTILE*2)   // 81920 B

template<int MODE, int WIDX, int AIDX>
__global__ __launch_bounds__(256)
void mgemm_k(int S) {
    extern __shared__ __align__(16) __nv_bfloat16 smg[];

    const __nv_bfloat16* Ah = (AIDX == 0) ? g_Ah0 : (AIDX == 1) ? g_Ah1 : g_Ah2;
    const __nv_bfloat16* Al = (AIDX == 0) ? g_Al0 : (AIDX == 1) ? g_Al1 : g_Al2;
    const __nv_bfloat16* Wh = g_Wth[WIDX];
    const __nv_bfloat16* Wl = g_Wtl[WIDX];

    int tid = threadIdx.x, wid = tid >> 5, lane = tid & 31;
    int wr = wid >> 2, wc = wid & 3;
    int qr = lane >> 2, qc = lane & 3;
    const int arow0 = blockIdx.y * 128, bcol0 = blockIdx.x * 128;

    float acc[4][4][4];
    #pragma unroll
    for (int mi = 0; mi < 4; mi++)
        #pragma unroll
        for (int ni = 0; ni < 4; ni++)
            #pragma unroll
            for (int e = 0; e < 4; e++) acc[mi][ni][e] = 0.f;

    auto stage = [&](int kt, int s) {
        __nv_bfloat16* dAh = smg + (size_t)s * 4 * GTILE;
        __nv_bfloat16* dAl = dAh + GTILE;
        __nv_bfloat16* dBh = dAl + GTILE;
        __nv_bfloat16* dBl = dBh + GTILE;
        #pragma unroll
        for (int v = 0; v < 2; v++) {
            int lin = tid + 256 * v;
            int r = lin >> 2, c = (lin & 3) * 8;
            size_t ga = (size_t)(arow0 + r) * DM + kt + c;
            size_t gb = (size_t)(bcol0 + r) * DM + kt + c;
            cpa16(&dAh[r * TSTR + c], Ah + ga);
            cpa16(&dAl[r * TSTR + c], Al + ga);
            cpa16(&dBh[r * TSTR + c], Wh + gb);
            cpa16(&dBl[r * TSTR + c], Wl + gb);
        }
    };

    stage(0, 0);
    CPA_COMMIT();

    const int NC = DM / KC;   // 32
    for (int c = 0; c < NC; c++) {
        if (c + 1 < NC) {
            stage((c + 1) * KC, (c + 1) & 1);
            CPA_COMMIT();
            CPA_WAIT1();
        } else {
            CPA_WAIT0();
        }
        __syncthreads();

        const __nv_bfloat16* sAh = smg + (size_t)(c & 1) * 4 * GTILE;
        const __nv_bfloat16* sAl = sAh + GTILE;
        const __nv_bfloat16* sBh = sAl + GTILE;
        const __nv_bfloat16* sBl = sBh + GTILE;

        #pragma unroll
        for (int k16 = 0; k16 < KC; k16 += 16) {
            int c0 = k16 + qc * 2;
            uint32_t af[4][4], bf[4][2];
            #pragma unroll
            for (int mi = 0; mi < 4; mi++) {
                int r0 = wr * 64 + mi * 16 + qr;
                af[mi][0] = *(uint32_t*)&sAh[r0 * TSTR + c0];
                af[mi][1] = *(uint32_t*)&sAh[(r0 + 8) * TSTR + c0];
                af[mi][2] = *(uint32_t*)&sAh[r0 * TSTR + c0 + 8];
                af[mi][3] = *(uint32_t*)&sAh[(r0 + 8) * TSTR + c0 + 8];
            }
            #pragma unroll
            for (int ni = 0; ni < 4; ni++) {
                int r0 = wc * 32 + ni * 8 + qr;
                bf[ni][0] = *(uint32_t*)&sBh[r0 * TSTR + c0];
                bf[ni][1] = *(uint32_t*)&sBh[r0 * TSTR + c0 + 8];
            }
            #pragma unroll
            for (int mi = 0; mi < 4; mi++)
                #pragma unroll
                for (int ni = 0; ni < 4; ni++)
                    MMA_BF16(acc[mi][ni], af[mi], bf[ni]);

            #pragma unroll
            for (int ni = 0; ni < 4; ni++) {
                int r0 = wc * 32 + ni * 8 + qr;
                bf[ni][0] = *(uint32_t*)&sBl[r0 * TSTR + c0];
                bf[ni][1] = *(uint32_t*)&sBl[r0 * TSTR + c0 + 8];
            }
            #pragma unroll
            for (int mi = 0; mi < 4; mi++)
                #pragma unroll
                for (int ni = 0; ni < 4; ni++)
                    MMA_BF16(acc[mi][ni], af[mi], bf[ni]);

            #pragma unroll
            for (int mi = 0; mi < 4; mi++) {
                int r0 = wr * 64 + mi * 16 + qr;
                af[mi][0] = *(uint32_t*)&sAl[r0 * TSTR + c0];
                af[mi][1] = *(uint32_t*)&sAl[(r0 + 8) * TSTR + c0];
                af[mi][2] = *(uint32_t*)&sAl[r0 * TSTR + c0 + 8];
                af[mi][3] = *(uint32_t*)&sAl[(r0 + 8) * TSTR + c0 + 8];
            }
            #pragma unroll
            for (int ni = 0; ni < 4; ni++) {
                int r0 = wc * 32 + ni * 8 + qr;
                bf[ni][0] = *(uint32_t*)&sBh[r0 * TSTR + c0];
                bf[ni][1] = *(uint32_t*)&sBh[r0 * TSTR + c0 + 8];
            }
            #pragma unroll
            for (int mi = 0; mi < 4; mi++)
                #pragma unroll
                for (int ni = 0; ni < 4; ni++)
                    MMA_BF16(acc[mi][ni], af[mi], bf[ni]);
        }
        __syncthreads();
    }

    // Epilogue
    #pragma unroll
    for (int mi = 0; mi < 4; mi++) {
        #pragma unroll
        for (int half = 0; half < 2; half++) {
            int m = arow0 + wr * 64 + mi * 16 + qr + half * 8;
            int bb = m / S, s = m - bb * S;
            #pragma unroll
            for (int ni = 0; ni < 4; ni++) {
                int n = bcol0 + wc * 32 + ni * 8 + qc * 2;   // even
                float o1 = acc[mi][ni][half * 2 + 0];
                float o2 = acc[mi][ni][half * 2 + 1];
                if (MODE == 3) {
                    g_proj[(size_t)m * DM + n]     = o1;
                    g_proj[(size_t)m * DM + n + 1] = o2;
                } else {
                    int hh = n >> 6, d0 = n & 63;
                    if (MODE == 0) {
                        size_t vb = ((size_t)(bb * NH + hh) * DH) * SKV + s;
                        __nv_bfloat16 h1 = __float2bfloat16(o1);
                        __nv_bfloat16 h2 = __float2bfloat16(o2);
                        g_VTh[vb + (size_t)d0 * SKV]       = h1;
                        g_VTh[vb + (size_t)(d0 + 1) * SKV] = h2;
                        g_VTl[vb + (size_t)d0 * SKV]       = __float2bfloat16(o1 - __bfloat162float(h1));
                        g_VTl[vb + (size_t)(d0 + 1) * SKV] = __float2bfloat16(o2 - __bfloat162float(h2));
                    } else {
                        int ti = s * 32 + (d0 >> 1);
                        float co = g_rc[ti], sn = g_rs[ti];
                        float r1 = o1 * co - o2 * sn;
                        float r2 = o2 * co + o1 * sn;
                        if (MODE == 1) { r1 *= 0.125f; r2 *= 0.125f; }
                        size_t base = ((size_t)(bb * NH + hh) * S + s) * DH + d0;
                        uint32_t hp, lp;
                        split2(r1, r2, hp, lp);
                        if (MODE == 1) {
                            *(uint32_t*)&g_Qbh[base] = hp;
                            *(uint32_t*)&g_Qbl[base] = lp;
                        } else {
                            *(uint32_t*)&g_Kbh[base] = hp;
                            *(uint32_t*)&g_Kbl[base] = lp;
                        }
                    }
                }
            }
        }
    }
}

// ---------------------------------------------------------------------------
// Tensor-core flash attention, cp.async double-buffered K/V.
// Grid (SQ/128, B*NH), 256 threads. Epilogue writes ctx directly as bf16
// hi/lo into g_Ah2/g_Al2 (the Wo-GEMM A operand).
// ---------------------------------------------------------------------------
#define TS2   72
#define QBYTES (128*TS2*2)         // one Q buffer (h or l): 18432
#define KVT    (64*TS2*2)          // one K/V tile: 9216
#define OKV    (2*QBYTES)          // 36864: start of KV stages
#define KVSTAGE (4*KVT)            // 36864 per stage (Kh,Kl,Vh,Vl)
#define OPEN   (OKV + 2*KVSTAGE)   // 110592
#define FSMEM  (OPEN + 2*64*4)     // 111104

__global__ __launch_bounds__(256)
void flash_k(const unsigned int* __restrict__ mask) {
    extern __shared__ __align__(16) char sm[];
    __nv_bfloat16* sQh = (__nv_bfloat16*)(sm);
    __nv_bfloat16* sQl = (__nv_bfloat16*)(sm + QBYTES);
    float* pen = (float*)(sm + OPEN);

    int tid = threadIdx.x, w = tid >> 5, lane = tid & 31;
    int r = lane >> 2, qc = lane & 3;
    int q0 = blockIdx.x * 128;
    int bh = blockIdx.y;
    int b = bh >> 4, h = bh & 15;
    int row0 = w * 16 + r;

    const __nv_bfloat16* Qh = g_Qbh + (size_t)bh * SQ * DH + (size_t)q0 * DH;
    const __nv_bfloat16* Ql = g_Qbl + (size_t)bh * SQ * DH + (size_t)q0 * DH;
    const __nv_bfloat16* Kh = g_Kbh + (size_t)bh * SKV * DH;
    const __nv_bfloat16* Kl = g_Kbl + (size_t)bh * SKV * DH;
    const __nv_bfloat16* Vh = g_VTh + (size_t)bh * DH * SKV;
    const __nv_bfloat16* Vl = g_VTl + (size_t)bh * DH * SKV;

    // stage Q tile (plain stores; first loop barrier orders them)
    #pragma unroll
    for (int v = 0; v < 4; v++) {
        int lin = tid + 256 * v;
        int rr = lin >> 3, c8 = (lin & 7) * 8;
        *(uint4*)&sQh[rr * TS2 + c8] = *(const uint4*)&Qh[rr * DH + c8];
        *(uint4*)&sQl[rr * TS2 + c8] = *(const uint4*)&Ql[rr * DH + c8];
    }

    // stage K/V chunk kc into KV stage s (cp.async) + mask pen (plain store)
    auto stage = [&](int kc, int s) {
        __nv_bfloat16* dKh = (__nv_bfloat16*)(sm + OKV + (size_t)s * KVSTAGE);
        __nv_bfloat16* dKl = dKh + 64 * TS2;
        __nv_bfloat16* dVh = dKl + 64 * TS2;
        __nv_bfloat16* dVl = dVh + 64 * TS2;
        #pragma unroll
        for (int v = 0; v < 2; v++) {
            int lin = tid + 256 * v;
            int rr = lin >> 3, c8 = (lin & 7) * 8;
            cpa16(&dKh[rr * TS2 + c8], &Kh[(size_t)(kc + rr) * DH + c8]);
            cpa16(&dKl[rr * TS2 + c8], &Kl[(size_t)(kc + rr) * DH + c8]);
            cpa16(&dVh[rr * TS2 + c8], &Vh[(size_t)rr * SKV + kc + c8]);
            cpa16(&dVl[rr * TS2 + c8], &Vl[(size_t)rr * SKV + kc + c8]);
        }
        if (tid < 64)
            pen[s * 64 + tid] = (mask[b * SKV + kc + tid] != 0u) ? 0.f : -1000000000.0f;
    };

    float m0 = -INFINITY, m1 = -INFINITY, l0 = 0.f, l1 = 0.f;
    float o[8][4];
    #pragma unroll
    for (int j = 0; j < 8; j++)
        #pragma unroll
        for (int e = 0; e < 4; e++) o[j][e] = 0.f;

    stage(0, 0);
    CPA_COMMIT();

    const int NC = SKV / 64;   // 32
    for (int c = 0; c < NC; c++) {
        if (c + 1 < NC) {
            stage((c + 1) * 64, (c + 1) & 1);
            CPA_COMMIT();
            CPA_WAIT1();
        } else {
            CPA_WAIT0();
        }
        __syncthreads();

        const __nv_bfloat16* sKh = (const __nv_bfloat16*)(sm + OKV + (size_t)(c & 1) * KVSTAGE);
        const __nv_bfloat16* sKl = sKh + 64 * TS2;
        const __nv_bfloat16* sVh = sKl + 64 * TS2;
        const __nv_bfloat16* sVl = sVh + 64 * TS2;
        const float* pn = pen + (c & 1) * 64;

        float sacc[8][4];
        #pragma unroll
        for (int j = 0; j < 8; j++)
            #pragma unroll
            for (int e = 0; e < 4; e++) sacc[j][e] = 0.f;

        #pragma unroll
        for (int t = 0; t < 4; t++) {
            int c0 = t * 16 + qc * 2;
            uint32_t ah[4], al[4];
            ah[0] = *(uint32_t*)&sQh[row0 * TS2 + c0];
            ah[1] = *(uint32_t*)&sQh[(row0 + 8) * TS2 + c0];
            ah[2] = *(uint32_t*)&sQh[row0 * TS2 + c0 + 8];
            ah[3] = *(uint32_t*)&sQh[(row0 + 8) * TS2 + c0 + 8];
            al[0] = *(uint32_t*)&sQl[row0 * TS2 + c0];
            al[1] = *(uint32_t*)&sQl[(row0 + 8) * TS2 + c0];
            al[2] = *(uint32_t*)&sQl[row0 * TS2 + c0 + 8];
            al[3] = *(uint32_t*)&sQl[(row0 + 8) * TS2 + c0 + 8];
            #pragma unroll
            for (int j = 0; j < 8; j++) {
                int kr = j * 8 + r;
                uint32_t bh2[2], bl2[2];
                bh2[0] = *(uint32_t*)&sKh[kr * TS2 + c0];
                bh2[1] = *(uint32_t*)&sKh[kr * TS2 + c0 + 8];
                bl2[0] = *(uint32_t*)&sKl[kr * TS2 + c0];
                bl2[1] = *(uint32_t*)&sKl[kr * TS2 + c0 + 8];
                MMA_BF16(sacc[j], ah, bh2);
                MMA_BF16(sacc[j], ah, bl2);
                MMA_BF16(sacc[j], al, bh2);
            }
        }

        #pragma unroll
        for (int j = 0; j < 8; j++) {
            float p0 = pn[j * 8 + qc * 2];
            float p1 = pn[j * 8 + qc * 2 + 1];
            sacc[j][0] += p0; sacc[j][1] += p1;
            sacc[j][2] += p0; sacc[j][3] += p1;
        }
        float mx0 = -INFINITY, mx1 = -INFINITY;
        #pragma unroll
        for (int j = 0; j < 8; j++) {
            mx0 = fmaxf(mx0, fmaxf(sacc[j][0], sacc[j][1]));
            mx1 = fmaxf(mx1, fmaxf(sacc[j][2], sacc[j][3]));
        }
        mx0 = fmaxf(mx0, __shfl_xor_sync(0xffffffffu, mx0, 1));
        mx0 = fmaxf(mx0, __shfl_xor_sync(0xffffffffu, mx0, 2));
        mx1 = fmaxf(mx1, __shfl_xor_sync(0xffffffffu, mx1, 1));
        mx1 = fmaxf(mx1, __shfl_xor_sync(0xffffffffu, mx1, 2));
        float nm0 = fmaxf(m0, mx0), nm1 = fmaxf(m1, mx1);
        float al0 = __expf(m0 - nm0), al1 = __expf(m1 - nm1);
        float s0 = 0.f, s1 = 0.f;
        #pragma unroll
        for (int j = 0; j < 8; j++) {
            sacc[j][0] = __expf(sacc[j][0] - nm0);
            sacc[j][1] = __expf(sacc[j][1] - nm0);
            sacc[j][2] = __expf(sacc[j][2] - nm1);
            sacc[j][3] = __expf(sacc[j][3] - nm1);
            s0 += sacc[j][0] + sacc[j][1];
            s1 += sacc[j][2] + sacc[j][3];
        }
        s0 += __shfl_xor_sync(0xffffffffu, s0, 1);
        s0 += __shfl_xor_sync(0xffffffffu, s0, 2);
        s1 += __shfl_xor_sync(0xffffffffu, s1, 1);
        s1 += __shfl_xor_sync(0xffffffffu, s1, 2);
        l0 = l0 * al0 + s0;  m0 = nm0;
        l1 = l1 * al1 + s1;  m1 = nm1;
        #pragma unroll
        for (int j = 0; j < 8; j++) {
            o[j][0] *= al0; o[j][1] *= al0;
            o[j][2] *= al1; o[j][3] *= al1;
        }

        #pragma unroll
        for (int t = 0; t < 4; t++) {
            uint32_t ph[4], pl[4];
            #pragma unroll
            for (int half = 0; half < 2; half++) {
                int jt = 2 * t + half;
                __nv_bfloat16 h0 = __float2bfloat16(sacc[jt][0]);
                __nv_bfloat16 h1 = __float2bfloat16(sacc[jt][1]);
                __nv_bfloat16 h2 = __float2bfloat16(sacc[jt][2]);
                __nv_bfloat16 h3 = __float2bfloat16(sacc[jt][3]);
                ph[half * 2 + 0] = (uint32_t)__bfloat16_as_ushort(h0) |
                                   ((uint32_t)__bfloat16_as_ushort(h1) << 16);
                ph[half * 2 + 1] = (uint32_t)__bfloat16_as_ushort(h2) |
                                   ((uint32_t)__bfloat16_as_ushort(h3) << 16);
                __nv_bfloat16 g0 = __float2bfloat16(sacc[jt][0] - __bfloat162float(h0));
                __nv_bfloat16 g1 = __float2bfloat16(sacc[jt][1] - __bfloat162float(h1));
                __nv_bfloat16 g2 = __float2bfloat16(sacc[jt][2] - __bfloat162float(h2));
                __nv_bfloat16 g3 = __float2bfloat16(sacc[jt][3] - __bfloat162float(h3));
                pl[half * 2 + 0] = (uint32_t)__bfloat16_as_ushort(g0) |
                                   ((uint32_t)__bfloat16_as_ushort(g1) << 16);
                pl[half * 2 + 1] = (uint32_t)__bfloat16_as_ushort(g2) |
                                   ((uint32_t)__bfloat16_as_ushort(g3) << 16);
            }
            int c0 = t * 16 + qc * 2;
            #pragma unroll
            for (int n = 0; n < 8; n++) {
                int dr = n * 8 + r;
                uint32_t bh2[2], bl2[2];
                bh2[0] = *(uint32_t*)&sVh[dr * TS2 + c0];
                bh2[1] = *(uint32_t*)&sVh[dr * TS2 + c0 + 8];
                bl2[0] = *(uint32_t*)&sVl[dr * TS2 + c0];
                bl2[1] = *(uint32_t*)&sVl[dr * TS2 + c0 + 8];
                MMA_BF16(o[n], ph, bh2);
                MMA_BF16(o[n], ph, bl2);
                MMA_BF16(o[n], pl, bh2);
            }
        }
        __syncthreads();   // all reads of this stage done before restage
    }

    // Epilogue: ctx split directly into Wo-GEMM A operands
    float inv0 = 1.0f / l0, inv1 = 1.0f / l1;
    #pragma unroll
    for (int n = 0; n < 8; n++) {
        int d = n * 8 + qc * 2;
        size_t a0 = ((size_t)b * SQ + q0 + row0) * DM + h * 64 + d;
        size_t a1 = ((size_t)b * SQ + q0 + row0 + 8) * DM + h * 64 + d;
        uint32_t hp, lp;
        split2(o[n][0] * inv0, o[n][1] * inv0, hp, lp);
        *(uint32_t*)&g_Ah2[a0] = hp;
        *(uint32_t*)&g_Al2[a0] = lp;
        split2(o[n][2] * inv1, o[n][3] * inv1, hp, lp);
        *(uint32_t*)&g_Ah2[a1] = hp;
        *(uint32_t*)&g_Al2[a1] = lp;
    }
}

// ---------------------------------------------------------------------------
// Residual + LayerNorm, one block per row.
// ---------------------------------------------------------------------------
__global__ __launch_bounds__(256)
void ln_k(const float* __restrict__ dq, const float* __restrict__ gamma,
          const float* __restrict__ beta, float* __restrict__ out) {
    int row = blockIdx.x;
    int tid = threadIdx.x;
    __shared__ float red[256];
    __shared__ float mu_s, var_s;

    float x[4];
    float s = 0.f;
    #pragma unroll
    for (int u = 0; u < 4; u++) {
        int idx = u * 256 + tid;
        x[u] = dq[(size_t)row * DM + idx] + g_proj[(size_t)row * DM + idx];
        s += x[u];
    }
    red[tid] = s;
    __syncthreads();
    for (int st = 128; st > 0; st >>= 1) {
        if (tid < st) red[tid] += red[tid + st];
        __syncthreads();
    }
    if (tid == 0) mu_s = red[0] * (1.0f / DM);
    __syncthreads();
    float mu = mu_s;

    s = 0.f;
    #pragma unroll
    for (int u = 0; u < 4; u++) {
        float d2 = x[u] - mu;
        s += d2 * d2;
    }
    red[tid] = s;
    __syncthreads();
    for (int st = 128; st > 0; st >>= 1) {
        if (tid < st) red[tid] += red[tid + st];
        __syncthreads();
    }
    if (tid == 0) var_s = red[0] * (1.0f / DM);
    __syncthreads();
    float rstd = rsqrtf(var_s + 0.001f);

    #pragma unroll
    for (int u = 0; u < 4; u++) {
        int idx = u * 256 + tid;
        out[(size_t)row * DM + idx] = (x[u] - mu) * rstd * gamma[idx] + beta[idx];
    }
}

// ---------------------------------------------------------------------------
extern "C" void kernel_launch(void* const* d_in, const int* in_sizes, int n_in,
                              void* d_out, int out_size) {
    const float* dq    = (const float*)d_in[0];
    const float* ekv   = (const float*)d_in[1];
    const unsigned int* mask = (const unsigned int*)d_in[2];
    const float* Wq    = (const float*)d_in[3];
    const float* Wk    = (const float*)d_in[4];
    const float* Wv    = (const float*)d_in[5];
    const float* Wo    = (const float*)d_in[6];
    const float* gamma = (const float*)d_in[7];
    const float* beta  = (const float*)d_in[8];
    float* out = (float*)d_out;

    cudaFuncSetAttribute(flash_k, cudaFuncAttributeMaxDynamicSharedMemorySize, FSMEM);
    cudaFuncSetAttribute(mgemm_k<1, 0, 0>, cudaFuncAttributeMaxDynamicSharedMemorySize, GSMEM);
    cudaFuncSetAttribute(mgemm_k<2, 1, 1>, cudaFuncAttributeMaxDynamicSharedMemorySize, GSMEM);
    cudaFuncSetAttribute(mgemm_k<0, 2, 1>, cudaFuncAttributeMaxDynamicSharedMemorySize, GSMEM);
    cudaFuncSetAttribute(mgemm_k<3, 3, 2>, cudaFuncAttributeMaxDynamicSharedMemorySize, GSMEM);

    // Prep
    rope_table_k<<<(SKV * 32 + 255) / 256, 256>>>();
    tsplit_k<0><<<dim3(32, 32), dim3(32, 8)>>>(Wq);
    tsplit_k<1><<<dim3(32, 32), dim3(32, 8)>>>(Wk);
    tsplit_k<2><<<dim3(32, 32), dim3(32, 8)>>>(Wv);
    tsplit_k<3><<<dim3(32, 32), dim3(32, 8)>>>(Wo);
    asplit_k<0><<<NA0 / 1024, 256>>>(dq);
    asplit_k<1><<<NA1 / 1024, 256>>>(ekv);

    // Projections + RoPE
    mgemm_k<1, 0, 0><<<dim3(8, 32), 256, GSMEM>>>(SQ);
    mgemm_k<2, 1, 1><<<dim3(8, 64), 256, GSMEM>>>(SKV);
    mgemm_k<0, 2, 1><<<dim3(8, 64), 256, GSMEM>>>(SKV);

    // Tensor-core flash attention (ctx split fused into epilogue)
    flash_k<<<dim3(SQ / 128, Bb * NH), 256, FSMEM>>>(mask);

    // Output projection
    mgemm_k<3, 3, 2><<<dim3(8, 32), 256, GSMEM>>>(SQ);

    // Residual + LayerNorm
    ln_k<<<Bb * SQ, 256>>>(dq, gamma, beta, out);
}

// round 15
// speedup vs baseline: 5.4762x; 2.0388x over previous
#include <cuda_runtime.h>
#include <cuda_bf16.h>
#include <math.h>
#include <stdint.h>

#define Bb 4
#define SQ 1024
#define SKV 2048
#define DM 1024
#define NH 16
#define DH 64

#define NA0 (Bb*SQ*DM)    // dq / ctx element count
#define NA1 (Bb*SKV*DM)   // ekv element count

// ---------------------------------------------------------------------------
// Scratch (device globals; referenced ONLY inside device code — never passed
// as kernel args from host).
// ---------------------------------------------------------------------------
__device__ __align__(16) float g_proj[Bb*SQ*DM];     // [B,Sq,DM]
__device__ __align__(16) float g_rc[SKV*32];         // rope cos [s][pair]
__device__ __align__(16) float g_rs[SKV*32];         // rope sin [s][pair]
// transposed [N,K] bf16 weights: 0=Wq 1=Wk 2=Wv 3=Wo
__device__ __align__(16) __nv_bfloat16 g_Wt[4][DM*DM];
// bf16 activations (GEMM A operands): 0=dq 1=ekv 2=ctx(from flash)
__device__ __align__(16) __nv_bfloat16 g_Ab0[NA0];
__device__ __align__(16) __nv_bfloat16 g_Ab1[NA1];
__device__ __align__(16) __nv_bfloat16 g_Ab2[NA0];
// attention operands (bf16)
__device__ __align__(16) __nv_bfloat16 g_Qb[Bb*NH*SQ*DH];    // [b,h,s,d]
__device__ __align__(16) __nv_bfloat16 g_Kb[Bb*NH*SKV*DH];   // [b,h,s,d]
__device__ __align__(16) __nv_bfloat16 g_VT[Bb*NH*DH*SKV];   // [b,h,d,s]

// ---------------------------------------------------------------------------
// mma.sync bf16: D(16x8) += A(16x16,row) * B(16x8,col), fp32 accum
// ---------------------------------------------------------------------------
#define MMA_BF16(d, a, b) \
    asm volatile("mma.sync.aligned.m16n8k16.row.col.f32.bf16.bf16.f32 " \
        "{%0,%1,%2,%3}, {%4,%5,%6,%7}, {%8,%9}, {%0,%1,%2,%3};" \
        : "+f"((d)[0]), "+f"((d)[1]), "+f"((d)[2]), "+f"((d)[3]) \
        : "r"((a)[0]), "r"((a)[1]), "r"((a)[2]), "r"((a)[3]), \
          "r"((b)[0]), "r"((b)[1]))

__device__ __forceinline__ uint32_t pack2(float a, float b) {
    __nv_bfloat16 ha = __float2bfloat16(a), hb = __float2bfloat16(b);
    return (uint32_t)__bfloat16_as_ushort(ha) | ((uint32_t)__bfloat16_as_ushort(hb) << 16);
}

__device__ __forceinline__ void cpa16(void* dst, const void* src) {
    uint32_t sa = (uint32_t)__cvta_generic_to_shared(dst);
    asm volatile("cp.async.cg.shared.global [%0], [%1], 16;" :: "r"(sa), "l"(src));
}
#define CPA_COMMIT() asm volatile("cp.async.commit_group;" ::: "memory")
#define CPA_WAIT1()  asm volatile("cp.async.wait_group 1;" ::: "memory")
#define CPA_WAIT0()  asm volatile("cp.async.wait_group 0;" ::: "memory")

// ---------------------------------------------------------------------------
// Prep
// ---------------------------------------------------------------------------
__global__ void rope_table_k() {
    int idx = blockIdx.x * blockDim.x + threadIdx.x;
    if (idx >= SKV * 32) return;
    int s = idx >> 5, p = idx & 31;
    double inv = pow(10000.0, -(double)(2 * p) / 64.0);
    double ang = (double)s * inv;
    g_rc[idx] = (float)cos(ang);
    g_rs[idx] = (float)sin(ang);
}

template<int WIDX>
__global__ void tsplit_k(const float* __restrict__ W) {
    __shared__ float t[32][33];
    int n0 = blockIdx.x * 32, k0 = blockIdx.y * 32;
    int tx = threadIdx.x, ty = threadIdx.y;    // 32 x 8
    #pragma unroll
    for (int r = 0; r < 32; r += 8)
        t[ty + r][tx] = W[(k0 + ty + r) * DM + n0 + tx];
    __syncthreads();
    __nv_bfloat16* T = g_Wt[WIDX];
    #pragma unroll
    for (int r = 0; r < 32; r += 8)
        T[(n0 + ty + r) * DM + k0 + tx] = __float2bfloat16(t[tx][ty + r]);
}

// activation convert: DST 0=dq 1=ekv
template<int DST>
__global__ void asplit_k(const float* __restrict__ X) {
    int i = (blockIdx.x * blockDim.x + threadIdx.x) * 4;
    __nv_bfloat16* Ab = (DST == 0) ? g_Ab0 : g_Ab1;
    float4 v = *(const float4*)(X + i);
    *(uint2*)&Ab[i] = make_uint2(pack2(v.x, v.y), pack2(v.z, v.w));
}

// ---------------------------------------------------------------------------
// mma.sync GEMM, cp.async double-buffered, single-pass bf16.
// MODE 0: V -> g_VT (transposed)  MODE 1: Q (rope+0.125) -> g_Qb
// MODE 2: K (rope) -> g_Kb        MODE 3: -> g_proj (fp32)
// Tile 128x128, KC=32, 8 warps, warp tile 64x32.
// ---------------------------------------------------------------------------
#define KC    32
#define TSTR  40
#define GTILE (128*TSTR)
#define GSMEM (2*2*GTILE*2)   // 2 stages x 2 tiles x bf16 = 40960 B

template<int MODE, int WIDX, int AIDX>
__global__ __launch_bounds__(256)
void mgemm_k(int S) {
    extern __shared__ __align__(16) __nv_bfloat16 smg[];

    const __nv_bfloat16* Ab = (AIDX == 0) ? g_Ab0 : (AIDX == 1) ? g_Ab1 : g_Ab2;
    const __nv_bfloat16* Wt = g_Wt[WIDX];

    int tid = threadIdx.x, wid = tid >> 5, lane = tid & 31;
    int wr = wid >> 2, wc = wid & 3;
    int qr = lane >> 2, qc = lane & 3;
    const int arow0 = blockIdx.y * 128, bcol0 = blockIdx.x * 128;

    float acc[4][4][4];
    #pragma unroll
    for (int mi = 0; mi < 4; mi++)
        #pragma unroll
        for (int ni = 0; ni < 4; ni++)
            #pragma unroll
            for (int e = 0; e < 4; e++) acc[mi][ni][e] = 0.f;

    auto stage = [&](int kt, int s) {
        __nv_bfloat16* dA = smg + (size_t)s * 2 * GTILE;
        __nv_bfloat16* dB = dA + GTILE;
        #pragma unroll
        for (int v = 0; v < 2; v++) {
            int lin = tid + 256 * v;
            int r = lin >> 2, c = (lin & 3) * 8;
            cpa16(&dA[r * TSTR + c], Ab + (size_t)(arow0 + r) * DM + kt + c);
            cpa16(&dB[r * TSTR + c], Wt + (size_t)(bcol0 + r) * DM + kt + c);
        }
    };

    stage(0, 0);
    CPA_COMMIT();

    const int NC = DM / KC;   // 32
    for (int c = 0; c < NC; c++) {
        if (c + 1 < NC) {
            stage((c + 1) * KC, (c + 1) & 1);
            CPA_COMMIT();
            CPA_WAIT1();
        } else {
            CPA_WAIT0();
        }
        __syncthreads();

        const __nv_bfloat16* sA = smg + (size_t)(c & 1) * 2 * GTILE;
        const __nv_bfloat16* sB = sA + GTILE;

        #pragma unroll
        for (int k16 = 0; k16 < KC; k16 += 16) {
            int c0 = k16 + qc * 2;
            uint32_t af[4][4], bf[4][2];
            #pragma unroll
            for (int mi = 0; mi < 4; mi++) {
                int r0 = wr * 64 + mi * 16 + qr;
                af[mi][0] = *(uint32_t*)&sA[r0 * TSTR + c0];
                af[mi][1] = *(uint32_t*)&sA[(r0 + 8) * TSTR + c0];
                af[mi][2] = *(uint32_t*)&sA[r0 * TSTR + c0 + 8];
                af[mi][3] = *(uint32_t*)&sA[(r0 + 8) * TSTR + c0 + 8];
            }
            #pragma unroll
            for (int ni = 0; ni < 4; ni++) {
                int r0 = wc * 32 + ni * 8 + qr;
                bf[ni][0] = *(uint32_t*)&sB[r0 * TSTR + c0];
                bf[ni][1] = *(uint32_t*)&sB[r0 * TSTR + c0 + 8];
            }
            #pragma unroll
            for (int mi = 0; mi < 4; mi++)
                #pragma unroll
                for (int ni = 0; ni < 4; ni++)
                    MMA_BF16(acc[mi][ni], af[mi], bf[ni]);
        }
        __syncthreads();
    }

    // Epilogue
    #pragma unroll
    for (int mi = 0; mi < 4; mi++) {
        #pragma unroll
        for (int half = 0; half < 2; half++) {
            int m = arow0 + wr * 64 + mi * 16 + qr + half * 8;
            int bb = m / S, s = m - bb * S;
            #pragma unroll
            for (int ni = 0; ni < 4; ni++) {
                int n = bcol0 + wc * 32 + ni * 8 + qc * 2;   // even
                float o1 = acc[mi][ni][half * 2 + 0];
                float o2 = acc[mi][ni][half * 2 + 1];
                if (MODE == 3) {
                    g_proj[(size_t)m * DM + n]     = o1;
                    g_proj[(size_t)m * DM + n + 1] = o2;
                } else {
                    int hh = n >> 6, d0 = n & 63;
                    if (MODE == 0) {
                        size_t vb = ((size_t)(bb * NH + hh) * DH) * SKV + s;
                        g_VT[vb + (size_t)d0 * SKV]       = __float2bfloat16(o1);
                        g_VT[vb + (size_t)(d0 + 1) * SKV] = __float2bfloat16(o2);
                    } else {
                        int ti = s * 32 + (d0 >> 1);
                        float co = g_rc[ti], sn = g_rs[ti];
                        float r1 = o1 * co - o2 * sn;
                        float r2 = o2 * co + o1 * sn;
                        if (MODE == 1) { r1 *= 0.125f; r2 *= 0.125f; }
                        size_t base = ((size_t)(bb * NH + hh) * S + s) * DH + d0;
                        uint32_t hp = pack2(r1, r2);
                        if (MODE == 1) *(uint32_t*)&g_Qb[base] = hp;
                        else           *(uint32_t*)&g_Kb[base] = hp;
                    }
                }
            }
        }
    }
}

// ---------------------------------------------------------------------------
// Tensor-core flash attention, cp.async double-buffered K/V, single-pass bf16.
// Grid (SQ/128, B*NH), 256 threads. Epilogue writes bf16 ctx into g_Ab2.
// ---------------------------------------------------------------------------
#define TS2   72
#define QBYTES (128*TS2*2)         // Q buffer: 18432
#define KVT    (64*TS2*2)          // one K/V tile: 9216
#define OKV    QBYTES
#define KVSTAGE (2*KVT)            // 18432 per stage (K,V)
#define OPEN   (OKV + 2*KVSTAGE)
#define FSMEM  (OPEN + 2*64*4)

__global__ __launch_bounds__(256)
void flash_k(const unsigned int* __restrict__ mask) {
    extern __shared__ __align__(16) char sm[];
    __nv_bfloat16* sQ = (__nv_bfloat16*)(sm);
    float* pen = (float*)(sm + OPEN);

    int tid = threadIdx.x, w = tid >> 5, lane = tid & 31;
    int r = lane >> 2, qc = lane & 3;
    int q0 = blockIdx.x * 128;
    int bh = blockIdx.y;
    int b = bh >> 4, h = bh & 15;
    int row0 = w * 16 + r;

    const __nv_bfloat16* Q = g_Qb + (size_t)bh * SQ * DH + (size_t)q0 * DH;
    const __nv_bfloat16* K = g_Kb + (size_t)bh * SKV * DH;
    const __nv_bfloat16* V = g_VT + (size_t)bh * DH * SKV;

    // stage Q tile (plain stores; first loop barrier orders them)
    #pragma unroll
    for (int v = 0; v < 4; v++) {
        int lin = tid + 256 * v;
        int rr = lin >> 3, c8 = (lin & 7) * 8;
        *(uint4*)&sQ[rr * TS2 + c8] = *(const uint4*)&Q[rr * DH + c8];
    }

    auto stage = [&](int kc, int s) {
        __nv_bfloat16* dK = (__nv_bfloat16*)(sm + OKV + (size_t)s * KVSTAGE);
        __nv_bfloat16* dV = dK + 64 * TS2;
        #pragma unroll
        for (int v = 0; v < 2; v++) {
            int lin = tid + 256 * v;
            int rr = lin >> 3, c8 = (lin & 7) * 8;
            cpa16(&dK[rr * TS2 + c8], &K[(size_t)(kc + rr) * DH + c8]);
            cpa16(&dV[rr * TS2 + c8], &V[(size_t)rr * SKV + kc + c8]);
        }
        if (tid < 64)
            pen[s * 64 + tid] = (mask[b * SKV + kc + tid] != 0u) ? 0.f : -1000000000.0f;
    };

    float m0 = -INFINITY, m1 = -INFINITY, l0 = 0.f, l1 = 0.f;
    float o[8][4];
    #pragma unroll
    for (int j = 0; j < 8; j++)
        #pragma unroll
        for (int e = 0; e < 4; e++) o[j][e] = 0.f;

    stage(0, 0);
    CPA_COMMIT();

    const int NC = SKV / 64;   // 32
    for (int c = 0; c < NC; c++) {
        if (c + 1 < NC) {
            stage((c + 1) * 64, (c + 1) & 1);
            CPA_COMMIT();
            CPA_WAIT1();
        } else {
            CPA_WAIT0();
        }
        __syncthreads();

        const __nv_bfloat16* sK = (const __nv_bfloat16*)(sm + OKV + (size_t)(c & 1) * KVSTAGE);
        const __nv_bfloat16* sV = sK + 64 * TS2;
        const float* pn = pen + (c & 1) * 64;

        float sacc[8][4];
        #pragma unroll
        for (int j = 0; j < 8; j++)
            #pragma unroll
            for (int e = 0; e < 4; e++) sacc[j][e] = 0.f;

        #pragma unroll
        for (int t = 0; t < 4; t++) {
            int c0 = t * 16 + qc * 2;
            uint32_t ah[4];
            ah[0] = *(uint32_t*)&sQ[row0 * TS2 + c0];
            ah[1] = *(uint32_t*)&sQ[(row0 + 8) * TS2 + c0];
            ah[2] = *(uint32_t*)&sQ[row0 * TS2 + c0 + 8];
            ah[3] = *(uint32_t*)&sQ[(row0 + 8) * TS2 + c0 + 8];
            #pragma unroll
            for (int j = 0; j < 8; j++) {
                int kr = j * 8 + r;
                uint32_t bh2[2];
                bh2[0] = *(uint32_t*)&sK[kr * TS2 + c0];
                bh2[1] = *(uint32_t*)&sK[kr * TS2 + c0 + 8];
                MMA_BF16(sacc[j], ah, bh2);
            }
        }

        #pragma unroll
        for (int j = 0; j < 8; j++) {
            float p0 = pn[j * 8 + qc * 2];
            float p1 = pn[j * 8 + qc * 2 + 1];
            sacc[j][0] += p0; sacc[j][1] += p1;
            sacc[j][2] += p0; sacc[j][3] += p1;
        }
        float mx0 = -INFINITY, mx1 = -INFINITY;
        #pragma unroll
        for (int j = 0; j < 8; j++) {
            mx0 = fmaxf(mx0, fmaxf(sacc[j][0], sacc[j][1]));
            mx1 = fmaxf(mx1, fmaxf(sacc[j][2], sacc[j][3]));
        }
        mx0 = fmaxf(mx0, __shfl_xor_sync(0xffffffffu, mx0, 1));
        mx0 = fmaxf(mx0, __shfl_xor_sync(0xffffffffu, mx0, 2));
        mx1 = fmaxf(mx1, __shfl_xor_sync(0xffffffffu, mx1, 1));
        mx1 = fmaxf(mx1, __shfl_xor_sync(0xffffffffu, mx1, 2));
        float nm0 = fmaxf(m0, mx0), nm1 = fmaxf(m1, mx1);
        float al0 = __expf(m0 - nm0), al1 = __expf(m1 - nm1);
        float s0 = 0.f, s1 = 0.f;
        #pragma unroll
        for (int j = 0; j < 8; j++) {
            sacc[j][0] = __expf(sacc[j][0] - nm0);
            sacc[j][1] = __expf(sacc[j][1] - nm0);
            sacc[j][2] = __expf(sacc[j][2] - nm1);
            sacc[j][3] = __expf(sacc[j][3] - nm1);
            s0 += sacc[j][0] + sacc[j][1];
            s1 += sacc[j][2] + sacc[j][3];
        }
        s0 += __shfl_xor_sync(0xffffffffu, s0, 1);
        s0 += __shfl_xor_sync(0xffffffffu, s0, 2);
        s1 += __shfl_xor_sync(0xffffffffu, s1, 1);
        s1 += __shfl_xor_sync(0xffffffffu, s1, 2);
        l0 = l0 * al0 + s0;  m0 = nm0;
        l1 = l1 * al1 + s1;  m1 = nm1;
        #pragma unroll
        for (int j = 0; j < 8; j++) {
            o[j][0] *= al0; o[j][1] *= al0;
            o[j][2] *= al1; o[j][3] *= al1;
        }

        #pragma unroll
        for (int t = 0; t < 4; t++) {
            uint32_t ph[4];
            #pragma unroll
            for (int half = 0; half < 2; half++) {
                int jt = 2 * t + half;
                ph[half * 2 + 0] = pack2(sacc[jt][0], sacc[jt][1]);
                ph[half * 2 + 1] = pack2(sacc[jt][2], sacc[jt][3]);
            }
            int c0 = t * 16 + qc * 2;
            #pragma unroll
            for (int n = 0; n < 8; n++) {
                int dr = n * 8 + r;
                uint32_t bh2[2];
                bh2[0] = *(uint32_t*)&sV[dr * TS2 + c0];
                bh2[1] = *(uint32_t*)&sV[dr * TS2 + c0 + 8];
                MMA_BF16(o[n], ph, bh2);
            }
        }
        __syncthreads();   // all reads of this stage done before restage
    }

    // Epilogue: ctx (bf16) directly into Wo-GEMM A operand
    float inv0 = 1.0f / l0, inv1 = 1.0f / l1;
    #pragma unroll
    for (int n = 0; n < 8; n++) {
        int d = n * 8 + qc * 2;
        size_t a0 = ((size_t)b * SQ + q0 + row0) * DM + h * 64 + d;
        size_t a1 = ((size_t)b * SQ + q0 + row0 + 8) * DM + h * 64 + d;
        *(uint32_t*)&g_Ab2[a0] = pack2(o[n][0] * inv0, o[n][1] * inv0);
        *(uint32_t*)&g_Ab2[a1] = pack2(o[n][2] * inv1, o[n][3] * inv1);
    }
}

// ---------------------------------------------------------------------------
// Residual + LayerNorm: one block per row, float4, single-pass sum/sumsq.
// ---------------------------------------------------------------------------
__global__ __launch_bounds__(256)
void ln_k(const float* __restrict__ dq, const float* __restrict__ gamma,
          const float* __restrict__ beta, float* __restrict__ out) {
    int row = blockIdx.x;
    int tid = threadIdx.x;
    int wid = tid >> 5, lane = tid & 31;
    __shared__ float ws[8], ws2[8];

    float4 a = *(const float4*)&dq[(size_t)row * DM + tid * 4];
    float4 p = *(const float4*)&g_proj[(size_t)row * DM + tid * 4];
    float x0 = a.x + p.x, x1 = a.y + p.y, x2 = a.z + p.z, x3 = a.w + p.w;
    float s  = x0 + x1 + x2 + x3;
    float s2 = x0 * x0 + x1 * x1 + x2 * x2 + x3 * x3;
    #pragma unroll
    for (int off = 16; off >= 1; off >>= 1) {
        s  += __shfl_xor_sync(0xffffffffu, s,  off);
        s2 += __shfl_xor_sync(0xffffffffu, s2, off);
    }
    if (lane == 0) { ws[wid] = s; ws2[wid] = s2; }
    __syncthreads();
    float tot = 0.f, tot2 = 0.f;
    #pragma unroll
    for (int k = 0; k < 8; k++) { tot += ws[k]; tot2 += ws2[k]; }
    float mu = tot * (1.0f / DM);
    float var = tot2 * (1.0f / DM) - mu * mu;
    float rstd = rsqrtf(var + 0.001f);

    float4 g = *(const float4*)&gamma[tid * 4];
    float4 be = *(const float4*)&beta[tid * 4];
    float4 res;
    res.x = (x0 - mu) * rstd * g.x + be.x;
    res.y = (x1 - mu) * rstd * g.y + be.y;
    res.z = (x2 - mu) * rstd * g.z + be.z;
    res.w = (x3 - mu) * rstd * g.w + be.w;
    *(float4*)&out[(size_t)row * DM + tid * 4] = res;
}

// ---------------------------------------------------------------------------
extern "C" void kernel_launch(void* const* d_in, const int* in_sizes, int n_in,
                              void* d_out, int out_size) {
    const float* dq    = (const float*)d_in[0];
    const float* ekv   = (const float*)d_in[1];
    const unsigned int* mask = (const unsigned int*)d_in[2];
    const float* Wq    = (const float*)d_in[3];
    const float* Wk    = (const float*)d_in[4];
    const float* Wv    = (const float*)d_in[5];
    const float* Wo    = (const float*)d_in[6];
    const float* gamma = (const float*)d_in[7];
    const float* beta  = (const float*)d_in[8];
    float* out = (float*)d_out;

    cudaFuncSetAttribute(flash_k, cudaFuncAttributeMaxDynamicSharedMemorySize, FSMEM);
    cudaFuncSetAttribute(mgemm_k<1, 0, 0>, cudaFuncAttributeMaxDynamicSharedMemorySize, GSMEM);
    cudaFuncSetAttribute(mgemm_k<2, 1, 1>, cudaFuncAttributeMaxDynamicSharedMemorySize, GSMEM);
    cudaFuncSetAttribute(mgemm_k<0, 2, 1>, cudaFuncAttributeMaxDynamicSharedMemorySize, GSMEM);
    cudaFuncSetAttribute(mgemm_k<3, 3, 2>, cudaFuncAttributeMaxDynamicSharedMemorySize, GSMEM);

    // Prep
    rope_table_k<<<(SKV * 32 + 255) / 256, 256>>>();
    tsplit_k<0><<<dim3(32, 32), dim3(32, 8)>>>(Wq);
    tsplit_k<1><<<dim3(32, 32), dim3(32, 8)>>>(Wk);
    tsplit_k<2><<<dim3(32, 32), dim3(32, 8)>>>(Wv);
    tsplit_k<3><<<dim3(32, 32), dim3(32, 8)>>>(Wo);
    asplit_k<0><<<NA0 / 1024, 256>>>(dq);
    asplit_k<1><<<NA1 / 1024, 256>>>(ekv);

    // Projections + RoPE
    mgemm_k<1, 0, 0><<<dim3(8, 32), 256, GSMEM>>>(SQ);
    mgemm_k<2, 1, 1><<<dim3(8, 64), 256, GSMEM>>>(SKV);
    mgemm_k<0, 2, 1><<<dim3(8, 64), 256, GSMEM>>>(SKV);

    // Tensor-core flash attention
    flash_k<<<dim3(SQ / 128, Bb * NH), 256, FSMEM>>>(mask);

    // Output projection
    mgemm_k<3, 3, 2><<<dim3(8, 32), 256, GSMEM>>>(SQ);

    // Residual + LayerNorm
    ln_k<<<Bb * SQ, 256>>>(dq, gamma, beta, out);
}

// round 16
// speedup vs baseline: 5.9512x; 1.0867x over previous
#include <cuda_runtime.h>
#include <cuda_bf16.h>
#include <math.h>
#include <stdint.h>

#define Bb 4
#define SQ 1024
#define SKV 2048
#define DM 1024
#define NH 16
#define DH 64

#define NA0 (Bb*SQ*DM)    // dq / ctx element count
#define NA1 (Bb*SKV*DM)   // ekv element count

// ---------------------------------------------------------------------------
// Scratch (device globals; referenced ONLY inside device code).
// ---------------------------------------------------------------------------
__device__ __align__(16) float g_proj[Bb*SQ*DM];     // [B,Sq,DM]
__device__ __align__(16) float g_rc[SKV*32];         // rope cos [s][pair]
__device__ __align__(16) float g_rs[SKV*32];         // rope sin [s][pair]
__device__ __align__(16) __nv_bfloat16 g_Wt[4][DM*DM];   // [N,K]: Wq Wk Wv Wo
__device__ __align__(16) __nv_bfloat16 g_Ab0[NA0];       // dq bf16
__device__ __align__(16) __nv_bfloat16 g_Ab1[NA1];       // ekv bf16
__device__ __align__(16) __nv_bfloat16 g_Ab2[NA0];       // ctx bf16 (from flash)
__device__ __align__(16) __nv_bfloat16 g_Qb[Bb*NH*SQ*DH];    // [b,h,s,d]
__device__ __align__(16) __nv_bfloat16 g_Kb[Bb*NH*SKV*DH];   // [b,h,s,d]
__device__ __align__(16) __nv_bfloat16 g_VT[Bb*NH*DH*SKV];   // [b,h,d,s]

// ---------------------------------------------------------------------------
// mma.sync bf16 + ldmatrix helpers
// ---------------------------------------------------------------------------
#define MMA_BF16(d, a, b) \
    asm volatile("mma.sync.aligned.m16n8k16.row.col.f32.bf16.bf16.f32 " \
        "{%0,%1,%2,%3}, {%4,%5,%6,%7}, {%8,%9}, {%0,%1,%2,%3};" \
        : "+f"((d)[0]), "+f"((d)[1]), "+f"((d)[2]), "+f"((d)[3]) \
        : "r"((a)[0]), "r"((a)[1]), "r"((a)[2]), "r"((a)[3]), \
          "r"((b)[0]), "r"((b)[1]))

#define LDMX4(r0, r1, r2, r3, addr) \
    asm volatile("ldmatrix.sync.aligned.m8n8.x4.shared.b16 {%0,%1,%2,%3}, [%4];" \
        : "=r"(r0), "=r"(r1), "=r"(r2), "=r"(r3) : "r"(addr))

__device__ __forceinline__ uint32_t sptr(const void* p) {
    return (uint32_t)__cvta_generic_to_shared(p);
}

__device__ __forceinline__ uint32_t pack2(float a, float b) {
    __nv_bfloat16 ha = __float2bfloat16(a), hb = __float2bfloat16(b);
    return (uint32_t)__bfloat16_as_ushort(ha) | ((uint32_t)__bfloat16_as_ushort(hb) << 16);
}

__device__ __forceinline__ void cpa16(void* dst, const void* src) {
    uint32_t sa = sptr(dst);
    asm volatile("cp.async.cg.shared.global [%0], [%1], 16;" :: "r"(sa), "l"(src));
}
#define CPA_COMMIT() asm volatile("cp.async.commit_group;" ::: "memory")
#define CPA_WAIT1()  asm volatile("cp.async.wait_group 1;" ::: "memory")
#define CPA_WAIT0()  asm volatile("cp.async.wait_group 0;" ::: "memory")

// ---------------------------------------------------------------------------
// Prep
// ---------------------------------------------------------------------------
__global__ void rope_table_k() {
    __shared__ double sinv[32];
    int tid = threadIdx.x;
    if (tid < 32) sinv[tid] = pow(10000.0, -(double)(2 * tid) / 64.0);
    __syncthreads();
    int idx = blockIdx.x * blockDim.x + tid;
    if (idx >= SKV * 32) return;
    int s = idx >> 5, p = idx & 31;
    double ang = (double)s * sinv[p];
    g_rc[idx] = (float)cos(ang);
    g_rs[idx] = (float)sin(ang);
}

// all 4 weights in one launch; blockIdx.z selects
__global__ void wsplit_k(const float* __restrict__ W0, const float* __restrict__ W1,
                         const float* __restrict__ W2, const float* __restrict__ W3) {
    __shared__ float t[32][33];
    int z = blockIdx.z;
    const float* W = (z == 0) ? W0 : (z == 1) ? W1 : (z == 2) ? W2 : W3;
    int n0 = blockIdx.x * 32, k0 = blockIdx.y * 32;
    int tx = threadIdx.x, ty = threadIdx.y;    // 32 x 8
    #pragma unroll
    for (int r = 0; r < 32; r += 8)
        t[ty + r][tx] = W[(k0 + ty + r) * DM + n0 + tx];
    __syncthreads();
    __nv_bfloat16* T = g_Wt[z];
    #pragma unroll
    for (int r = 0; r < 32; r += 8)
        T[(n0 + ty + r) * DM + k0 + tx] = __float2bfloat16(t[tx][ty + r]);
}

// dq + ekv in one launch
__global__ void asplit_k(const float* __restrict__ Xq, const float* __restrict__ Xkv) {
    int i = (blockIdx.x * blockDim.x + threadIdx.x) * 4;
    const float* src;
    __nv_bfloat16* dst;
    int off;
    if (i < NA0) { src = Xq;  dst = g_Ab0; off = i; }
    else         { src = Xkv; dst = g_Ab1; off = i - NA0; }
    float4 v = *(const float4*)(src + off);
    *(uint2*)&dst[off] = make_uint2(pack2(v.x, v.y), pack2(v.z, v.w));
}

// ---------------------------------------------------------------------------
// GEMM core (cp.async double-buffered, ldmatrix frag loads).
// mode 0: V -> g_VT (transposed)  mode 1: Q (rope+0.125) -> g_Qb
// mode 2: K (rope) -> g_Kb        mode 3: -> g_proj (fp32)
// Tile 128x128, KC=32, 8 warps, warp tile 64x32.
// ---------------------------------------------------------------------------
#define KC    32
#define TSTR  40
#define GTILE (128*TSTR)
#define GSMEM (2*2*GTILE*2)   // 40960 B

__device__ __forceinline__ void gemm_body(
    int mode, const __nv_bfloat16* __restrict__ Ab, const __nv_bfloat16* __restrict__ Wt,
    int S, int arow0, int bcol0, __nv_bfloat16* smg)
{
    int tid = threadIdx.x, wid = tid >> 5, lane = tid & 31;
    int wr = wid >> 2, wc = wid & 3;
    int qr = lane >> 2, qc = lane & 3;
    int l15 = lane & 15, lhi = (lane >> 4) * 8;

    float acc[4][4][4];
    #pragma unroll
    for (int mi = 0; mi < 4; mi++)
        #pragma unroll
        for (int ni = 0; ni < 4; ni++)
            #pragma unroll
            for (int e = 0; e < 4; e++) acc[mi][ni][e] = 0.f;

    auto stage = [&](int kt, int s) {
        __nv_bfloat16* dA = smg + (size_t)s * 2 * GTILE;
        __nv_bfloat16* dB = dA + GTILE;
        #pragma unroll
        for (int v = 0; v < 2; v++) {
            int lin = tid + 256 * v;
            int r = lin >> 2, c = (lin & 3) * 8;
            cpa16(&dA[r * TSTR + c], Ab + (size_t)(arow0 + r) * DM + kt + c);
            cpa16(&dB[r * TSTR + c], Wt + (size_t)(bcol0 + r) * DM + kt + c);
        }
    };

    stage(0, 0);
    CPA_COMMIT();

    const int NC = DM / KC;   // 32
    for (int c = 0; c < NC; c++) {
        if (c + 1 < NC) {
            stage((c + 1) * KC, (c + 1) & 1);
            CPA_COMMIT();
            CPA_WAIT1();
        } else {
            CPA_WAIT0();
        }
        __syncthreads();

        const __nv_bfloat16* sA = smg + (size_t)(c & 1) * 2 * GTILE;
        const __nv_bfloat16* sB = sA + GTILE;

        #pragma unroll
        for (int k16 = 0; k16 < KC; k16 += 16) {
            int c0 = k16 + lhi;
            uint32_t af[4][4], bf[4][2];
            #pragma unroll
            for (int mi = 0; mi < 4; mi++) {
                uint32_t a = sptr(&sA[(wr * 64 + mi * 16 + l15) * TSTR + c0]);
                LDMX4(af[mi][0], af[mi][1], af[mi][2], af[mi][3], a);
            }
            #pragma unroll
            for (int np = 0; np < 2; np++) {   // n-frag pairs (0,1) and (2,3)
                uint32_t a = sptr(&sB[(wc * 32 + np * 16 + l15) * TSTR + c0]);
                uint32_t t0, t1, t2, t3;
                LDMX4(t0, t1, t2, t3, a);
                bf[np * 2 + 0][0] = t0; bf[np * 2 + 0][1] = t2;
                bf[np * 2 + 1][0] = t1; bf[np * 2 + 1][1] = t3;
            }
            #pragma unroll
            for (int mi = 0; mi < 4; mi++)
                #pragma unroll
                for (int ni = 0; ni < 4; ni++)
                    MMA_BF16(acc[mi][ni], af[mi], bf[ni]);
        }
        __syncthreads();
    }

    // Epilogue
    #pragma unroll
    for (int mi = 0; mi < 4; mi++) {
        #pragma unroll
        for (int half = 0; half < 2; half++) {
            int m = arow0 + wr * 64 + mi * 16 + qr + half * 8;
            int bb = m / S, s = m - bb * S;
            #pragma unroll
            for (int ni = 0; ni < 4; ni++) {
                int n = bcol0 + wc * 32 + ni * 8 + qc * 2;   // even
                float o1 = acc[mi][ni][half * 2 + 0];
                float o2 = acc[mi][ni][half * 2 + 1];
                if (mode == 3) {
                    g_proj[(size_t)m * DM + n]     = o1;
                    g_proj[(size_t)m * DM + n + 1] = o2;
                } else {
                    int hh = n >> 6, d0 = n & 63;
                    if (mode == 0) {
                        size_t vb = ((size_t)(bb * NH + hh) * DH) * SKV + s;
                        g_VT[vb + (size_t)d0 * SKV]       = __float2bfloat16(o1);
                        g_VT[vb + (size_t)(d0 + 1) * SKV] = __float2bfloat16(o2);
                    } else {
                        int ti = s * 32 + (d0 >> 1);
                        float co = g_rc[ti], sn = g_rs[ti];
                        float r1 = o1 * co - o2 * sn;
                        float r2 = o2 * co + o1 * sn;
                        if (mode == 1) { r1 *= 0.125f; r2 *= 0.125f; }
                        size_t base = ((size_t)(bb * NH + hh) * S + s) * DH + d0;
                        uint32_t hp = pack2(r1, r2);
                        if (mode == 1) *(uint32_t*)&g_Qb[base] = hp;
                        else           *(uint32_t*)&g_Kb[base] = hp;
                    }
                }
            }
        }
    }
}

// merged Q/K/V projections: grid (8, 160). y<32: Q, y<96: K, else V.
__global__ __launch_bounds__(256)
void projgemm_k() {
    extern __shared__ __align__(16) __nv_bfloat16 smg[];
    int y = blockIdx.y;
    int mode, S, arow0;
    const __nv_bfloat16 *Ab, *Wt;
    if (y < 32)      { mode = 1; Ab = g_Ab0; Wt = g_Wt[0]; S = SQ;  arow0 = y * 128; }
    else if (y < 96) { mode = 2; Ab = g_Ab1; Wt = g_Wt[1]; S = SKV; arow0 = (y - 32) * 128; }
    else             { mode = 0; Ab = g_Ab1; Wt = g_Wt[2]; S = SKV; arow0 = (y - 96) * 128; }
    gemm_body(mode, Ab, Wt, S, arow0, blockIdx.x * 128, smg);
}

// output projection: ctx @ Wo
__global__ __launch_bounds__(256)
void ogemm_k() {
    extern __shared__ __align__(16) __nv_bfloat16 smg[];
    gemm_body(3, g_Ab2, g_Wt[3], SQ, blockIdx.y * 128, blockIdx.x * 128, smg);
}

// ---------------------------------------------------------------------------
// Tensor-core flash attention, cp.async double-buffered K/V, ldmatrix loads.
// Grid (SQ/128, B*NH), 256 threads. Epilogue writes bf16 ctx into g_Ab2.
// ---------------------------------------------------------------------------
#define TS2   72
#define QBYTES (128*TS2*2)
#define KVT    (64*TS2*2)
#define OKV    QBYTES
#define KVSTAGE (2*KVT)
#define OPEN   (OKV + 2*KVSTAGE)
#define FSMEM  (OPEN + 2*64*4)

__global__ __launch_bounds__(256)
void flash_k(const unsigned int* __restrict__ mask) {
    extern __shared__ __align__(16) char sm[];
    __nv_bfloat16* sQ = (__nv_bfloat16*)(sm);
    float* pen = (float*)(sm + OPEN);

    int tid = threadIdx.x, w = tid >> 5, lane = tid & 31;
    int r = lane >> 2, qc = lane & 3;
    int l15 = lane & 15, lhi = (lane >> 4) * 8;
    int q0 = blockIdx.x * 128;
    int bh = blockIdx.y;
    int b = bh >> 4, h = bh & 15;
    int row0 = w * 16 + r;

    const __nv_bfloat16* Q = g_Qb + (size_t)bh * SQ * DH + (size_t)q0 * DH;
    const __nv_bfloat16* K = g_Kb + (size_t)bh * SKV * DH;
    const __nv_bfloat16* V = g_VT + (size_t)bh * DH * SKV;

    #pragma unroll
    for (int v = 0; v < 4; v++) {
        int lin = tid + 256 * v;
        int rr = lin >> 3, c8 = (lin & 7) * 8;
        *(uint4*)&sQ[rr * TS2 + c8] = *(const uint4*)&Q[rr * DH + c8];
    }

    auto stage = [&](int kc, int s) {
        __nv_bfloat16* dK = (__nv_bfloat16*)(sm + OKV + (size_t)s * KVSTAGE);
        __nv_bfloat16* dV = dK + 64 * TS2;
        #pragma unroll
        for (int v = 0; v < 2; v++) {
            int lin = tid + 256 * v;
            int rr = lin >> 3, c8 = (lin & 7) * 8;
            cpa16(&dK[rr * TS2 + c8], &K[(size_t)(kc + rr) * DH + c8]);
            cpa16(&dV[rr * TS2 + c8], &V[(size_t)rr * SKV + kc + c8]);
        }
        if (tid < 64)
            pen[s * 64 + tid] = (mask[b * SKV + kc + tid] != 0u) ? 0.f : -1000000000.0f;
    };

    float m0 = -INFINITY, m1 = -INFINITY, l0 = 0.f, l1 = 0.f;
    float o[8][4];
    #pragma unroll
    for (int j = 0; j < 8; j++)
        #pragma unroll
        for (int e = 0; e < 4; e++) o[j][e] = 0.f;

    stage(0, 0);
    CPA_COMMIT();

    const int NC = SKV / 64;   // 32
    for (int c = 0; c < NC; c++) {
        if (c + 1 < NC) {
            stage((c + 1) * 64, (c + 1) & 1);
            CPA_COMMIT();
            CPA_WAIT1();
        } else {
            CPA_WAIT0();
        }
        __syncthreads();

        const __nv_bfloat16* sK = (const __nv_bfloat16*)(sm + OKV + (size_t)(c & 1) * KVSTAGE);
        const __nv_bfloat16* sV = sK + 64 * TS2;
        const float* pn = pen + (c & 1) * 64;

        float sacc[8][4];
        #pragma unroll
        for (int j = 0; j < 8; j++)
            #pragma unroll
            for (int e = 0; e < 4; e++) sacc[j][e] = 0.f;

        #pragma unroll
        for (int t = 0; t < 4; t++) {
            int c0 = t * 16 + lhi;
            uint32_t ah[4];
            LDMX4(ah[0], ah[1], ah[2], ah[3],
                  sptr(&sQ[(w * 16 + l15) * TS2 + c0]));
            #pragma unroll
            for (int jp = 0; jp < 4; jp++) {   // key-frag pairs
                uint32_t t0, t1, t2, t3;
                LDMX4(t0, t1, t2, t3, sptr(&sK[(jp * 16 + l15) * TS2 + c0]));
                uint32_t b0[2] = {t0, t2}, b1[2] = {t1, t3};
                MMA_BF16(sacc[jp * 2 + 0], ah, b0);
                MMA_BF16(sacc[jp * 2 + 1], ah, b1);
            }
        }

        #pragma unroll
        for (int j = 0; j < 8; j++) {
            float p0 = pn[j * 8 + qc * 2];
            float p1 = pn[j * 8 + qc * 2 + 1];
            sacc[j][0] += p0; sacc[j][1] += p1;
            sacc[j][2] += p0; sacc[j][3] += p1;
        }
        float mx0 = -INFINITY, mx1 = -INFINITY;
        #pragma unroll
        for (int j = 0; j < 8; j++) {
            mx0 = fmaxf(mx0, fmaxf(sacc[j][0], sacc[j][1]));
            mx1 = fmaxf(mx1, fmaxf(sacc[j][2], sacc[j][3]));
        }
        mx0 = fmaxf(mx0, __shfl_xor_sync(0xffffffffu, mx0, 1));
        mx0 = fmaxf(mx0, __shfl_xor_sync(0xffffffffu, mx0, 2));
        mx1 = fmaxf(mx1, __shfl_xor_sync(0xffffffffu, mx1, 1));
        mx1 = fmaxf(mx1, __shfl_xor_sync(0xffffffffu, mx1, 2));
        float nm0 = fmaxf(m0, mx0), nm1 = fmaxf(m1, mx1);
        float al0 = __expf(m0 - nm0), al1 = __expf(m1 - nm1);
        float s0 = 0.f, s1 = 0.f;
        #pragma unroll
        for (int j = 0; j < 8; j++) {
            sacc[j][0] = __expf(sacc[j][0] - nm0);
            sacc[j][1] = __expf(sacc[j][1] - nm0);
            sacc[j][2] = __expf(sacc[j][2] - nm1);
            sacc[j][3] = __expf(sacc[j][3] - nm1);
            s0 += sacc[j][0] + sacc[j][1];
            s1 += sacc[j][2] + sacc[j][3];
        }
        s0 += __shfl_xor_sync(0xffffffffu, s0, 1);
        s0 += __shfl_xor_sync(0xffffffffu, s0, 2);
        s1 += __shfl_xor_sync(0xffffffffu, s1, 1);
        s1 += __shfl_xor_sync(0xffffffffu, s1, 2);
        l0 = l0 * al0 + s0;  m0 = nm0;
        l1 = l1 * al1 + s1;  m1 = nm1;
        #pragma unroll
        for (int j = 0; j < 8; j++) {
            o[j][0] *= al0; o[j][1] *= al0;
            o[j][2] *= al1; o[j][3] *= al1;
        }

        #pragma unroll
        for (int t = 0; t < 4; t++) {
            uint32_t ph[4];
            #pragma unroll
            for (int half = 0; half < 2; half++) {
                int jt = 2 * t + half;
                ph[half * 2 + 0] = pack2(sacc[jt][0], sacc[jt][1]);
                ph[half * 2 + 1] = pack2(sacc[jt][2], sacc[jt][3]);
            }
            int c0 = t * 16 + lhi;
            #pragma unroll
            for (int np = 0; np < 4; np++) {   // d-frag pairs
                uint32_t t0, t1, t2, t3;
                LDMX4(t0, t1, t2, t3, sptr(&sV[(np * 16 + l15) * TS2 + c0]));
                uint32_t b0[2] = {t0, t2}, b1[2] = {t1, t3};
                MMA_BF16(o[np * 2 + 0], ph, b0);
                MMA_BF16(o[np * 2 + 1], ph, b1);
            }
        }
        __syncthreads();
    }

    // Epilogue: ctx (bf16) directly into Wo-GEMM A operand
    float inv0 = 1.0f / l0, inv1 = 1.0f / l1;
    #pragma unroll
    for (int n = 0; n < 8; n++) {
        int d = n * 8 + qc * 2;
        size_t a0 = ((size_t)b * SQ + q0 + row0) * DM + h * 64 + d;
        size_t a1 = ((size_t)b * SQ + q0 + row0 + 8) * DM + h * 64 + d;
        *(uint32_t*)&g_Ab2[a0] = pack2(o[n][0] * inv0, o[n][1] * inv0);
        *(uint32_t*)&g_Ab2[a1] = pack2(o[n][2] * inv1, o[n][3] * inv1);
    }
}

// ---------------------------------------------------------------------------
// Residual + LayerNorm: one block per row, float4, single-pass sum/sumsq.
// ---------------------------------------------------------------------------
__global__ __launch_bounds__(256)
void ln_k(const float* __restrict__ dq, const float* __restrict__ gamma,
          const float* __restrict__ beta, float* __restrict__ out) {
    int row = blockIdx.x;
    int tid = threadIdx.x;
    int wid = tid >> 5, lane = tid & 31;
    __shared__ float ws[8], ws2[8];

    float4 a = *(const float4*)&dq[(size_t)row * DM + tid * 4];
    float4 p = *(const float4*)&g_proj[(size_t)row * DM + tid * 4];
    float x0 = a.x + p.x, x1 = a.y + p.y, x2 = a.z + p.z, x3 = a.w + p.w;
    float s  = x0 + x1 + x2 + x3;
    float s2 = x0 * x0 + x1 * x1 + x2 * x2 + x3 * x3;
    #pragma unroll
    for (int off = 16; off >= 1; off >>= 1) {
        s  += __shfl_xor_sync(0xffffffffu, s,  off);
        s2 += __shfl_xor_sync(0xffffffffu, s2, off);
    }
    if (lane == 0) { ws[wid] = s; ws2[wid] = s2; }
    __syncthreads();
    float tot = 0.f, tot2 = 0.f;
    #pragma unroll
    for (int k = 0; k < 8; k++) { tot += ws[k]; tot2 += ws2[k]; }
    float mu = tot * (1.0f / DM);
    float var = tot2 * (1.0f / DM) - mu * mu;
    float rstd = rsqrtf(var + 0.001f);

    float4 g = *(const float4*)&gamma[tid * 4];
    float4 be = *(const float4*)&beta[tid * 4];
    float4 res;
    res.x = (x0 - mu) * rstd * g.x + be.x;
    res.y = (x1 - mu) * rstd * g.y + be.y;
    res.z = (x2 - mu) * rstd * g.z + be.z;
    res.w = (x3 - mu) * rstd * g.w + be.w;
    *(float4*)&out[(size_t)row * DM + tid * 4] = res;
}

// ---------------------------------------------------------------------------
extern "C" void kernel_launch(void* const* d_in, const int* in_sizes, int n_in,
                              void* d_out, int out_size) {
    const float* dq    = (const float*)d_in[0];
    const float* ekv   = (const float*)d_in[1];
    const unsigned int* mask = (const unsigned int*)d_in[2];
    const float* Wq    = (const float*)d_in[3];
    const float* Wk    = (const float*)d_in[4];
    const float* Wv    = (const float*)d_in[5];
    const float* Wo    = (const float*)d_in[6];
    const float* gamma = (const float*)d_in[7];
    const float* beta  = (const float*)d_in[8];
    float* out = (float*)d_out;

    cudaFuncSetAttribute(flash_k,    cudaFuncAttributeMaxDynamicSharedMemorySize, FSMEM);
    cudaFuncSetAttribute(projgemm_k, cudaFuncAttributeMaxDynamicSharedMemorySize, GSMEM);
    cudaFuncSetAttribute(ogemm_k,    cudaFuncAttributeMaxDynamicSharedMemorySize, GSMEM);

    // Prep (merged)
    rope_table_k<<<(SKV * 32 + 255) / 256, 256>>>();
    wsplit_k<<<dim3(32, 32, 4), dim3(32, 8)>>>(Wq, Wk, Wv, Wo);
    asplit_k<<<(NA0 + NA1) / 1024, 256>>>(dq, ekv);

    // All three projections + RoPE in one launch
    projgemm_k<<<dim3(8, 160), 256, GSMEM>>>();

    // Tensor-core flash attention
    flash_k<<<dim3(SQ / 128, Bb * NH), 256, FSMEM>>>(mask);

    // Output projection
    ogemm_k<<<dim3(8, 32), 256, GSMEM>>>();

    // Residual + LayerNorm
    ln_k<<<Bb * SQ, 256>>>(dq, gamma, beta, out);
}